// round 5
// baseline (speedup 1.0000x reference)
#include <cuda_runtime.h>
#include <cstdint>

// ---------------- static scratch (no allocs allowed) ----------------
__device__ float g_xg[32768 * 3072];      // input-projection buffer (max 3H=3072)
__device__ float g_actB[32768 * 1024];    // raw GRU outputs (pre-LN)
__device__ unsigned g_h[64 * 1024];       // hidden state broadcast (tf32 bit patterns)
__device__ float g_psum[64 * 32768];      // per-CTA partial row sums
__device__ float g_psqs[64 * 32768];      // per-CTA partial row sumsq
__device__ float g_sum[32768];            // reduced row sums (prev layer output)
__device__ float g_sqs[32768];            // reduced row sumsq
__device__ unsigned g_arrive;
__device__ unsigned g_release;

// ---------------- helpers ----------------
__device__ __forceinline__ unsigned f2tf(float x) {
    unsigned r; asm("cvt.rna.tf32.f32 %0, %1;" : "=r"(r) : "f"(x)); return r;
}
__device__ __forceinline__ void mma8(float* c, const unsigned* a, const unsigned* b) {
    asm volatile("mma.sync.aligned.m16n8k8.row.col.f32.tf32.tf32.f32 "
                 "{%0,%1,%2,%3}, {%4,%5,%6,%7}, {%8,%9}, {%0,%1,%2,%3};"
                 : "+f"(c[0]), "+f"(c[1]), "+f"(c[2]), "+f"(c[3])
                 : "r"(a[0]), "r"(a[1]), "r"(a[2]), "r"(a[3]),
                   "r"(b[0]), "r"(b[1]));
}

// ---------------- input-projection GEMM with optional fused LN ----------------
// C[m,n] = sum_k LN(A[m,k]) * W[n,k];  A: [32768,K], W: [N,K], C -> g_xg [32768,N]
template<int K, bool LN>
__global__ void __launch_bounds__(256) gemm_xg(const float* __restrict__ A,
                                               const float* __restrict__ W,
                                               int N,
                                               const float* __restrict__ gma,
                                               const float* __restrict__ bta,
                                               int nprev) {
    __shared__ unsigned As[128 * 36];
    __shared__ unsigned Bs[64 * 36];
    __shared__ float gS[K], bS[K];
    __shared__ float rmS[128], rsS[128];

    const int m0 = blockIdx.y * 128;
    const int n0 = blockIdx.x * 64;
    const int tid = threadIdx.x;
    const int lane = tid & 31, wid = tid >> 5;
    const int wm = (wid & 3) * 32, wn = (wid >> 2) * 32;

    if (LN) {
        for (int i = tid; i < K; i += 256) { gS[i] = gma[i]; bS[i] = bta[i]; }
        if (tid < 128) {
            int m = m0 + tid;
            float s, q;
            if ((m & 511) == 511) {          // last-step rows: reduce partials here
                s = 0.f; q = 0.f;
                for (int c = 0; c < nprev; c++) {
                    s += g_psum[(size_t)c * 32768 + m];
                    q += g_psqs[(size_t)c * 32768 + m];
                }
            } else {
                s = g_sum[m]; q = g_sqs[m];
            }
            float mean = s * (1.f / K);
            float var = q * (1.f / K) - mean * mean;
            rmS[tid] = mean;
            rsS[tid] = rsqrtf(var);
        }
        __syncthreads();
    }

    float acc[2][4][4];
#pragma unroll
    for (int i = 0; i < 2; i++)
#pragma unroll
        for (int j = 0; j < 4; j++)
#pragma unroll
            for (int k = 0; k < 4; k++) acc[i][j][k] = 0.f;

    const int lr = tid >> 3;
    const int lc = (tid & 7) * 4;

    for (int kc = 0; kc < K; kc += 32) {
#pragma unroll
        for (int i = 0; i < 4; i++) {
            int r = lr + i * 32;
            float4 v = *reinterpret_cast<const float4*>(&A[(size_t)(m0 + r) * K + kc + lc]);
            if (LN) {
                float mm = rmS[r], ss = rsS[r];
                int k = kc + lc;
                v.x = (v.x - mm) * ss * gS[k]     + bS[k];
                v.y = (v.y - mm) * ss * gS[k + 1] + bS[k + 1];
                v.z = (v.z - mm) * ss * gS[k + 2] + bS[k + 2];
                v.w = (v.w - mm) * ss * gS[k + 3] + bS[k + 3];
            }
            As[r * 36 + lc + 0] = f2tf(v.x); As[r * 36 + lc + 1] = f2tf(v.y);
            As[r * 36 + lc + 2] = f2tf(v.z); As[r * 36 + lc + 3] = f2tf(v.w);
        }
#pragma unroll
        for (int i = 0; i < 2; i++) {
            int r = lr + i * 32;
            float4 v = *reinterpret_cast<const float4*>(&W[(size_t)(n0 + r) * K + kc + lc]);
            Bs[r * 36 + lc + 0] = f2tf(v.x); Bs[r * 36 + lc + 1] = f2tf(v.y);
            Bs[r * 36 + lc + 2] = f2tf(v.z); Bs[r * 36 + lc + 3] = f2tf(v.w);
        }
        __syncthreads();
#pragma unroll
        for (int k8 = 0; k8 < 4; k8++) {
            const int kb = k8 * 8;
            unsigned a[2][4], b[4][2];
#pragma unroll
            for (int mf = 0; mf < 2; mf++) {
                int rb = wm + mf * 16 + (lane >> 2);
                a[mf][0] = As[rb * 36 + kb + (lane & 3)];
                a[mf][1] = As[(rb + 8) * 36 + kb + (lane & 3)];
                a[mf][2] = As[rb * 36 + kb + (lane & 3) + 4];
                a[mf][3] = As[(rb + 8) * 36 + kb + (lane & 3) + 4];
            }
#pragma unroll
            for (int nf = 0; nf < 4; nf++) {
                int cb = wn + nf * 8 + (lane >> 2);
                b[nf][0] = Bs[cb * 36 + kb + (lane & 3)];
                b[nf][1] = Bs[cb * 36 + kb + (lane & 3) + 4];
            }
#pragma unroll
            for (int mf = 0; mf < 2; mf++)
#pragma unroll
                for (int nf = 0; nf < 4; nf++)
                    mma8(acc[mf][nf], a[mf], b[nf]);
        }
        __syncthreads();
    }
#pragma unroll
    for (int mf = 0; mf < 2; mf++)
#pragma unroll
        for (int nf = 0; nf < 4; nf++) {
            int row = m0 + wm + mf * 16 + (lane >> 2);
            int col = n0 + wn + nf * 8 + 2 * (lane & 3);
            g_xg[(size_t)row * N + col]     = acc[mf][nf][0];
            g_xg[(size_t)row * N + col + 1] = acc[mf][nf][1];
            g_xg[(size_t)(row + 8) * N + col]     = acc[mf][nf][2];
            g_xg[(size_t)(row + 8) * N + col + 1] = acc[mf][nf][3];
        }
}

// ---------------- persistent GRU recurrence ----------------
// grid = H/16 CTAs (co-resident), 256 threads (8 warps, 4M x 2N).
// Mainloop: register-double-buffered staging of h (tf32 bits) + mma.sync.
// Epilogue: warps 0-1 (lane = batch row) gates + stores + LN partials;
//           warps 2-3 reduce previous step's LN partials into g_sum/g_sqs.
template<int H>
__global__ void __launch_bounds__(256, 1) gru_rec(const float* __restrict__ Whh) {
    constexpr int WSP = H + 4;
    constexpr int NCH = H / 32;
    constexpr int NC  = H / 16;          // == gridDim.x
    constexpr int RPC = 64 / NC;
    extern __shared__ unsigned char smem_raw[];
    unsigned* Ws = reinterpret_cast<unsigned*>(smem_raw);    // [48][WSP]
    unsigned* As = Ws + 48 * WSP;                            // 2 x [64][36]
    float* hgS = reinterpret_cast<float*>(As + 2 * 64 * 36); // [64][52]

    const float* xg = g_xg;
    float* y = g_actB;
    const int tid = threadIdx.x;
    const int lane = tid & 31, wid = tid >> 5;
    const int wm = (wid & 3) * 16;
    const int wn = (wid >> 2) * 24;
    const int cta = blockIdx.x;
    const int c0 = cta * 16;
    const int q = lane >> 2, r4 = lane & 3;
    const int rb = wm + q;

    // one-time: Whh slice -> SMEM (tf32)
    {
        constexpr int nf4 = H / 4;
        for (int idx = tid; idx < 48 * nf4; idx += 256) {
            int rr = idx / nf4;
            int c4 = (idx % nf4) * 4;
            int gate = rr >> 4;
            int jj = rr & 15;
            int grow = gate * H + c0 + jj;
            float4 v = *reinterpret_cast<const float4*>(&Whh[(size_t)grow * H + c4]);
            Ws[rr * WSP + c4 + 0] = f2tf(v.x); Ws[rr * WSP + c4 + 1] = f2tf(v.y);
            Ws[rr * WSP + c4 + 2] = f2tf(v.z); Ws[rr * WSP + c4 + 3] = f2tf(v.w);
        }
    }
    __syncthreads();

    // staging-copy index map: 512 float4 = 64 rows x 8 col-groups, 2 per thread
    const int i0r = tid >> 3,          i0c = (tid & 7) * 4;
    const int i1r = (tid + 256) >> 3,  i1c = (tid & 7) * 4;

    const int b = wid * 32 + lane;      // batch row for epilogue warps 0-1
    float hl[16];
#pragma unroll
    for (int i = 0; i < 16; i++) hl[i] = 0.f;

    float4 pxr[4], pxz[4], pxn[4];
#define PF_XG(TT) do { if (wid < 2) { \
        const float* xrow = xg + ((size_t)b * 512 + (TT)) * (size_t)(3 * H); \
        _Pragma("unroll") \
        for (int k = 0; k < 4; k++) { \
            pxr[k] = __ldcs(reinterpret_cast<const float4*>(xrow + c0 + 4 * k)); \
            pxz[k] = __ldcs(reinterpret_cast<const float4*>(xrow + H + c0 + 4 * k)); \
            pxn[k] = __ldcs(reinterpret_cast<const float4*>(xrow + 2 * H + c0 + 4 * k)); \
        } } } while (0)

    PF_XG(0);

    for (int t = 0; t < 512; t++) {
        float acc[3][4];
#pragma unroll
        for (int nf = 0; nf < 3; nf++)
#pragma unroll
            for (int k = 0; k < 4; k++) acc[nf][k] = 0.f;

        if (t > 0) {
            uint4 pre0, pre1;
            pre0 = __ldcg(reinterpret_cast<const uint4*>(&g_h[i0r * H + i0c]));
            pre1 = __ldcg(reinterpret_cast<const uint4*>(&g_h[i1r * H + i1c]));
            *reinterpret_cast<uint4*>(&As[i0r * 36 + i0c]) = pre0;
            *reinterpret_cast<uint4*>(&As[i1r * 36 + i1c]) = pre1;

            for (int ch = 0; ch < NCH; ch++) {
                __syncthreads();
                if (ch + 1 < NCH) {
                    const int kc = (ch + 1) * 32;
                    pre0 = __ldcg(reinterpret_cast<const uint4*>(&g_h[i0r * H + kc + i0c]));
                    pre1 = __ldcg(reinterpret_cast<const uint4*>(&g_h[i1r * H + kc + i1c]));
                }
                const unsigned* Ab = As + (ch & 1) * (64 * 36);
                const int kc = ch * 32;
#pragma unroll
                for (int k8 = 0; k8 < 4; k8++) {
                    const int kb = k8 * 8;
                    unsigned a[4], bb[3][2];
                    a[0] = Ab[rb * 36 + kb + r4];
                    a[1] = Ab[(rb + 8) * 36 + kb + r4];
                    a[2] = Ab[rb * 36 + kb + r4 + 4];
                    a[3] = Ab[(rb + 8) * 36 + kb + r4 + 4];
#pragma unroll
                    for (int nf = 0; nf < 3; nf++) {
                        int cb = wn + nf * 8 + q;
                        bb[nf][0] = Ws[cb * WSP + kc + kb + r4];
                        bb[nf][1] = Ws[cb * WSP + kc + kb + r4 + 4];
                    }
#pragma unroll
                    for (int nf = 0; nf < 3; nf++)
                        mma8(acc[nf], a, bb[nf]);
                }
                if (ch + 1 < NCH) {
                    unsigned* Bb = As + ((ch + 1) & 1) * (64 * 36);
                    *reinterpret_cast<uint4*>(&Bb[i0r * 36 + i0c]) = pre0;
                    *reinterpret_cast<uint4*>(&Bb[i1r * 36 + i1c]) = pre1;
                }
            }
        }
        // accumulators -> hg slice in SMEM
#pragma unroll
        for (int nf = 0; nf < 3; nf++) {
            int row = wm + q;
            int col = wn + nf * 8 + 2 * r4;
            hgS[row * 52 + col]           = acc[nf][0];
            hgS[row * 52 + col + 1]       = acc[nf][1];
            hgS[(row + 8) * 52 + col]     = acc[nf][2];
            hgS[(row + 8) * 52 + col + 1] = acc[nf][3];
        }
        __syncthreads();

        if (wid < 2) {
            // ---- gate epilogue: lane owns batch row b, 16 cols ----
            float hr[16], hz[16], hn[16], xr[16], xz[16], xn[16], hv[16];
            const float4* hp = reinterpret_cast<const float4*>(&hgS[b * 52]);
#pragma unroll
            for (int k = 0; k < 4; k++) {
                *reinterpret_cast<float4*>(&hr[4 * k]) = hp[k];
                *reinterpret_cast<float4*>(&hz[4 * k]) = hp[4 + k];
                *reinterpret_cast<float4*>(&hn[4 * k]) = hp[8 + k];
                *reinterpret_cast<float4*>(&xr[4 * k]) = pxr[k];
                *reinterpret_cast<float4*>(&xz[4 * k]) = pxz[k];
                *reinterpret_cast<float4*>(&xn[4 * k]) = pxn[k];
            }
            float ls = 0.f, lq = 0.f;
#pragma unroll
            for (int j = 0; j < 16; j++) {
                float r = 1.f / (1.f + __expf(-(xr[j] + hr[j])));
                float z = 1.f / (1.f + __expf(-(xz[j] + hz[j])));
                float n = tanhf(xn[j] + r * hn[j]);
                float h2 = (1.f - z) * n + z * hl[j];
                hl[j] = h2;
                hv[j] = h2;
                ls += h2;
                lq += h2 * h2;
            }
            size_t m = (size_t)b * 512 + t;
            float* yb = y + m * (size_t)H + c0;
            unsigned* hb = &g_h[b * H + c0];
#pragma unroll
            for (int k = 0; k < 4; k++) {
                *reinterpret_cast<float4*>(yb + 4 * k) =
                    make_float4(hv[4 * k], hv[4 * k + 1], hv[4 * k + 2], hv[4 * k + 3]);
                uint4 u = make_uint4(f2tf(hv[4 * k]), f2tf(hv[4 * k + 1]),
                                     f2tf(hv[4 * k + 2]), f2tf(hv[4 * k + 3]));
                __stcg(reinterpret_cast<uint4*>(hb + 4 * k), u);
            }
            __stcg(&g_psum[(size_t)cta * 32768 + m], ls);
            __stcg(&g_psqs[(size_t)cta * 32768 + m], lq);
        } else if (wid < 4 && t > 0) {
            // ---- warps 2-3: reduce LN partials of step t-1 (visible post-barrier) ----
            const float* Pp = (wid == 2) ? g_psum : g_psqs;
            float* Op = (wid == 2) ? g_sum : g_sqs;
            const int t1 = t - 1;
#pragma unroll
            for (int rr = 0; rr < RPC; rr++) {
                int br = cta + rr * NC;
                int m = br * 512 + t1;
                float v = 0.f;
                for (int c = lane; c < NC; c += 32)
                    v += __ldcg(&Pp[(size_t)c * 32768 + m]);
#pragma unroll
                for (int o = 16; o > 0; o >>= 1) v += __shfl_xor_sync(0xffffffffu, v, o);
                if (lane == 0) __stcg(&Op[m], v);
            }
        }

        if (t < 511) {
            PF_XG(t + 1);                  // independent of h; hides under barrier
            __syncthreads();
            if (tid == 0) {
                unsigned prev;
                asm volatile("atom.release.gpu.add.u32 %0, [%1], 1;"
                             : "=r"(prev) : "l"(&g_arrive) : "memory");
                unsigned tgt = (unsigned)NC * (unsigned)(t + 1);
                if (prev + 1u == tgt) {
                    asm volatile("st.release.gpu.u32 [%0], %1;"
                                 :: "l"(&g_release), "r"((unsigned)(t + 1)) : "memory");
                } else {
                    unsigned v;
                    do {
                        asm volatile("ld.acquire.gpu.u32 %0, [%1];"
                                     : "=r"(v) : "l"(&g_release) : "memory");
                    } while (v < (unsigned)(t + 1));
                }
            }
            __syncthreads();
        }
    }

    // final arrival round: last CTA resets counters (nobody waits)
    __syncthreads();
    if (tid == 0) {
        unsigned prev;
        asm volatile("atom.release.gpu.add.u32 %0, [%1], 1;"
                     : "=r"(prev) : "l"(&g_arrive) : "memory");
        if (prev + 1u == (unsigned)NC * 512u) {
            asm volatile("st.release.gpu.u32 [%0], %1;" :: "l"(&g_arrive), "r"(0u) : "memory");
            asm volatile("st.release.gpu.u32 [%0], %1;" :: "l"(&g_release), "r"(0u) : "memory");
        }
    }
#undef PF_XG
}

// ---------------- final LayerNorm (H=128, eps=0) ----------------
template<int H>
__global__ void __launch_bounds__(128) ln_k(const float* __restrict__ gw,
                                            const float* __restrict__ bw,
                                            float* __restrict__ outp) {
    constexpr int PER = H / 128;
    __shared__ float red[8];
    const int row = blockIdx.x, tid = threadIdx.x;
    const float* p = g_actB + (size_t)row * H;
    float v[PER];
    float s = 0.f;
#pragma unroll
    for (int i = 0; i < PER; i++) { v[i] = p[tid + i * 128]; s += v[i]; }
#pragma unroll
    for (int o = 16; o > 0; o >>= 1) s += __shfl_xor_sync(0xffffffffu, s, o);
    if ((tid & 31) == 0) red[tid >> 5] = s;
    __syncthreads();
    float mean = (red[0] + red[1] + red[2] + red[3]) * (1.f / H);
    float s2 = 0.f;
#pragma unroll
    for (int i = 0; i < PER; i++) { float d = v[i] - mean; s2 += d * d; }
#pragma unroll
    for (int o = 16; o > 0; o >>= 1) s2 += __shfl_xor_sync(0xffffffffu, s2, o);
    if ((tid & 31) == 0) red[4 + (tid >> 5)] = s2;
    __syncthreads();
    float var = (red[4] + red[5] + red[6] + red[7]) * (1.f / H);
    float inv = rsqrtf(var);
#pragma unroll
    for (int i = 0; i < PER; i++) {
        int c = tid + i * 128;
        outp[(size_t)row * H + c] = (v[i] - mean) * inv * gw[c] + bw[c];
    }
}

// ---------------- driver ----------------
static inline size_t rec_smem(int H) {
    return sizeof(unsigned) * (48 * (H + 4) + 2 * 64 * 36) + sizeof(float) * (64 * 52);
}

extern "C" void kernel_launch(void* const* d_in, const int* in_sizes, int n_in,
                              void* d_out, int out_size) {
    (void)in_sizes; (void)n_in; (void)out_size;
    const float* x = (const float*)d_in[0];
    const float* Wih[6]; const float* Whh[6]; const float* gw[6]; const float* bw[6];
    for (int l = 0; l < 6; l++) {
        Wih[l] = (const float*)d_in[1 + 4 * l];
        Whh[l] = (const float*)d_in[2 + 4 * l];
        gw[l]  = (const float*)d_in[3 + 4 * l];
        bw[l]  = (const float*)d_in[4 + 4 * l];
    }
    float* actB;
    cudaGetSymbolAddress((void**)&actB, g_actB);

    static const int DIN[6] = {128, 256, 512, 1024, 512, 256};
    static const int HH[6]  = {256, 512, 1024, 512, 256, 128};

    for (int l = 0; l < 6; l++) {
        const int K = DIN[l], H = HH[l], N = 3 * H;
        const float* A = (l == 0) ? x : (const float*)actB;
        const float* gma = (l == 0) ? nullptr : gw[l - 1];
        const float* bta = (l == 0) ? nullptr : bw[l - 1];
        const int nprev = (l == 0) ? 0 : HH[l - 1] / 16;
        dim3 grid(N / 64, 256);
        if (l == 0) {
            gemm_xg<128, false><<<grid, 256>>>(A, Wih[l], N, gma, bta, nprev);
        } else {
            switch (K) {
                case 256:  gemm_xg<256, true><<<grid, 256>>>(A, Wih[l], N, gma, bta, nprev); break;
                case 512:  gemm_xg<512, true><<<grid, 256>>>(A, Wih[l], N, gma, bta, nprev); break;
                case 1024: gemm_xg<1024, true><<<grid, 256>>>(A, Wih[l], N, gma, bta, nprev); break;
            }
        }
        const size_t sm = rec_smem(H);
        switch (H) {
            case 128:
                cudaFuncSetAttribute(gru_rec<128>, cudaFuncAttributeMaxDynamicSharedMemorySize, (int)sm);
                gru_rec<128><<<128 / 16, 256, sm>>>(Whh[l]); break;
            case 256:
                cudaFuncSetAttribute(gru_rec<256>, cudaFuncAttributeMaxDynamicSharedMemorySize, (int)sm);
                gru_rec<256><<<256 / 16, 256, sm>>>(Whh[l]); break;
            case 512:
                cudaFuncSetAttribute(gru_rec<512>, cudaFuncAttributeMaxDynamicSharedMemorySize, (int)sm);
                gru_rec<512><<<512 / 16, 256, sm>>>(Whh[l]); break;
            case 1024:
                cudaFuncSetAttribute(gru_rec<1024>, cudaFuncAttributeMaxDynamicSharedMemorySize, (int)sm);
                gru_rec<1024><<<1024 / 16, 256, sm>>>(Whh[l]); break;
        }
    }
    ln_k<128><<<32768, 128>>>(gw[5], bw[5], (float*)d_out);
}

// round 7
// speedup vs baseline: 1.5116x; 1.5116x over previous
#include <cuda_runtime.h>
#include <cstdint>

// ---------------- static scratch (no allocs allowed) ----------------
__device__ float g_xg[32768 * 3072];        // input-projection buffer (max 3H=3072)
__device__ float g_actB[32768 * 1024];      // raw GRU outputs (pre-LN)
__device__ unsigned g_h[2][64 * 1024];      // DOUBLE-BUFFERED hidden state (tf32 bits)
__device__ float g_psum[64 * 32768];        // per-CTA partial row sums
__device__ float g_psqs[64 * 32768];        // per-CTA partial row sumsq
__device__ float g_sum[32768];              // reduced row sums
__device__ float g_sqs[32768];              // reduced row sumsq
__device__ unsigned g_arr[64 * 32];         // decentralized barrier slots (128B stride)

// ---------------- helpers ----------------
__device__ __forceinline__ unsigned f2tf(float x) {
    unsigned r; asm("cvt.rna.tf32.f32 %0, %1;" : "=r"(r) : "f"(x)); return r;
}
__device__ __forceinline__ void mma8(float* c, const unsigned* a, const unsigned* b) {
    asm volatile("mma.sync.aligned.m16n8k8.row.col.f32.tf32.tf32.f32 "
                 "{%0,%1,%2,%3}, {%4,%5,%6,%7}, {%8,%9}, {%0,%1,%2,%3};"
                 : "+f"(c[0]), "+f"(c[1]), "+f"(c[2]), "+f"(c[3])
                 : "r"(a[0]), "r"(a[1]), "r"(a[2]), "r"(a[3]),
                   "r"(b[0]), "r"(b[1]));
}

// ---------------- input-projection GEMM with optional fused LN ----------------
// C[m,n] = sum_k LN(A[m,k]) * W[n,k];  A: [32768,K], W: [N,K], C -> g_xg [32768,N]
// LN stats from g_sum/g_sqs (shadow-reduced in prev recurrence); rows with
// (m&511)>=510 reduced here from per-CTA partials. Also resets barrier slots.
template<int K, bool LN>
__global__ void __launch_bounds__(256) gemm_xg(const float* __restrict__ A,
                                               const float* __restrict__ W,
                                               int N,
                                               const float* __restrict__ gma,
                                               const float* __restrict__ bta,
                                               int nprev) {
    __shared__ unsigned As[128 * 36];
    __shared__ unsigned Bs[64 * 36];
    __shared__ float gS[K], bS[K];
    __shared__ float rmS[128], rsS[128];

    const int m0 = blockIdx.y * 128;
    const int n0 = blockIdx.x * 64;
    const int tid = threadIdx.x;
    const int lane = tid & 31, wid = tid >> 5;
    const int wm = (wid & 3) * 32, wn = (wid >> 2) * 32;

    if (blockIdx.x == 0 && blockIdx.y == 0 && tid < 64)
        g_arr[tid * 32] = 0u;              // reset barrier slots for the next rec

    if (LN) {
        for (int i = tid; i < K; i += 256) { gS[i] = gma[i]; bS[i] = bta[i]; }
        if (tid < 128) {
            int m = m0 + tid;
            float s, q;
            if ((m & 511) >= 510) {
                s = 0.f; q = 0.f;
                for (int c = 0; c < nprev; c++) {
                    s += g_psum[(size_t)c * 32768 + m];
                    q += g_psqs[(size_t)c * 32768 + m];
                }
            } else {
                s = g_sum[m]; q = g_sqs[m];
            }
            float mean = s * (1.f / K);
            float var = q * (1.f / K) - mean * mean;
            rmS[tid] = mean;
            rsS[tid] = rsqrtf(var);
        }
        __syncthreads();
    }

    float acc[2][4][4];
#pragma unroll
    for (int i = 0; i < 2; i++)
#pragma unroll
        for (int j = 0; j < 4; j++)
#pragma unroll
            for (int k = 0; k < 4; k++) acc[i][j][k] = 0.f;

    const int lr = tid >> 3;
    const int lc = (tid & 7) * 4;

    for (int kc = 0; kc < K; kc += 32) {
#pragma unroll
        for (int i = 0; i < 4; i++) {
            int r = lr + i * 32;
            float4 v = *reinterpret_cast<const float4*>(&A[(size_t)(m0 + r) * K + kc + lc]);
            if (LN) {
                float mm = rmS[r], ss = rsS[r];
                int k = kc + lc;
                v.x = (v.x - mm) * ss * gS[k]     + bS[k];
                v.y = (v.y - mm) * ss * gS[k + 1] + bS[k + 1];
                v.z = (v.z - mm) * ss * gS[k + 2] + bS[k + 2];
                v.w = (v.w - mm) * ss * gS[k + 3] + bS[k + 3];
            }
            As[r * 36 + lc + 0] = f2tf(v.x); As[r * 36 + lc + 1] = f2tf(v.y);
            As[r * 36 + lc + 2] = f2tf(v.z); As[r * 36 + lc + 3] = f2tf(v.w);
        }
#pragma unroll
        for (int i = 0; i < 2; i++) {
            int r = lr + i * 32;
            float4 v = *reinterpret_cast<const float4*>(&W[(size_t)(n0 + r) * K + kc + lc]);
            Bs[r * 36 + lc + 0] = f2tf(v.x); Bs[r * 36 + lc + 1] = f2tf(v.y);
            Bs[r * 36 + lc + 2] = f2tf(v.z); Bs[r * 36 + lc + 3] = f2tf(v.w);
        }
        __syncthreads();
#pragma unroll
        for (int k8 = 0; k8 < 4; k8++) {
            const int kb = k8 * 8;
            unsigned a[2][4], b[4][2];
#pragma unroll
            for (int mf = 0; mf < 2; mf++) {
                int rb = wm + mf * 16 + (lane >> 2);
                a[mf][0] = As[rb * 36 + kb + (lane & 3)];
                a[mf][1] = As[(rb + 8) * 36 + kb + (lane & 3)];
                a[mf][2] = As[rb * 36 + kb + (lane & 3) + 4];
                a[mf][3] = As[(rb + 8) * 36 + kb + (lane & 3) + 4];
            }
#pragma unroll
            for (int nf = 0; nf < 4; nf++) {
                int cb = wn + nf * 8 + (lane >> 2);
                b[nf][0] = Bs[cb * 36 + kb + (lane & 3)];
                b[nf][1] = Bs[cb * 36 + kb + (lane & 3) + 4];
            }
#pragma unroll
            for (int mf = 0; mf < 2; mf++)
#pragma unroll
                for (int nf = 0; nf < 4; nf++)
                    mma8(acc[mf][nf], a[mf], b[nf]);
        }
        __syncthreads();
    }
#pragma unroll
    for (int mf = 0; mf < 2; mf++)
#pragma unroll
        for (int nf = 0; nf < 4; nf++) {
            int row = m0 + wm + mf * 16 + (lane >> 2);
            int col = n0 + wn + nf * 8 + 2 * (lane & 3);
            g_xg[(size_t)row * N + col]     = acc[mf][nf][0];
            g_xg[(size_t)row * N + col + 1] = acc[mf][nf][1];
            g_xg[(size_t)(row + 8) * N + col]     = acc[mf][nf][2];
            g_xg[(size_t)(row + 8) * N + col + 1] = acc[mf][nf][3];
        }
}

// ---------------- persistent GRU recurrence ----------------
// grid = H/16 CTAs (co-resident), 256 threads (8 warps, 4M x 2N) — round-3 blessed
// mainloop (bitwise-identical h arithmetic). KCH = k-chunk width (32 or 64; same
// ascending k order either way). g_h double-buffered: read buf[t&1], write buf[(t+1)&1].
// Decentralized barrier: per-CTA release slot; each thread tid<NC acquire-polls one slot.
// LN partials per step; shadow reduction of step t-1 on warps 4-7 during the poll.
template<int H, int KCH>
__global__ void __launch_bounds__(256, 1) gru_rec(const float* __restrict__ Whh) {
    constexpr int WSP  = H + 4;
    constexpr int ASTR = KCH + 4;
    constexpr int NCH  = H / KCH;
    constexpr int NC   = H / 16;         // == gridDim.x  (<= 64)
    constexpr int CG   = KCH / 4;        // col-groups per row
    constexpr int PFN  = KCH / 16;       // uint4 per thread per chunk
    extern __shared__ unsigned char smem_raw[];
    unsigned* Ws = reinterpret_cast<unsigned*>(smem_raw);      // [48][WSP]
    unsigned* As = Ws + 48 * WSP;                              // 2 x [64][ASTR]
    float* hgS = reinterpret_cast<float*>(As + 2 * 64 * ASTR); // [64][52]

    const float* xg = g_xg;
    float* y = g_actB;
    const int tid = threadIdx.x;
    const int lane = tid & 31, wid = tid >> 5;
    const int wm = (wid & 3) * 16;
    const int wn = (wid >> 2) * 24;
    const int cta = blockIdx.x;
    const int c0 = cta * 16;
    const int q = lane >> 2, r4 = lane & 3;
    const int rb = wm + q;

    // one-time: Whh slice -> SMEM (tf32)
    {
        constexpr int nf4 = H / 4;
        for (int idx = tid; idx < 48 * nf4; idx += 256) {
            int rr = idx / nf4;
            int c4 = (idx % nf4) * 4;
            int gate = rr >> 4;
            int jj = rr & 15;
            int grow = gate * H + c0 + jj;
            float4 v = *reinterpret_cast<const float4*>(&Whh[(size_t)grow * H + c4]);
            Ws[rr * WSP + c4 + 0] = f2tf(v.x); Ws[rr * WSP + c4 + 1] = f2tf(v.y);
            Ws[rr * WSP + c4 + 2] = f2tf(v.z); Ws[rr * WSP + c4 + 3] = f2tf(v.w);
        }
    }
    __syncthreads();

    const int j = tid & 15;
    const int bbase = tid >> 4;          // 0..15
    float hl[4] = {0.f, 0.f, 0.f, 0.f};
    float pxr[4], pxz[4], pxn[4];

#define PF_XG(TT) do { \
        _Pragma("unroll") \
        for (int it = 0; it < 4; it++) { \
            int bb = bbase + it * 16; \
            const float* xrow = xg + ((size_t)bb * 512 + (TT)) * (size_t)(3 * H); \
            pxr[it] = __ldcs(xrow + c0 + j); \
            pxz[it] = __ldcs(xrow + H + c0 + j); \
            pxn[it] = __ldcs(xrow + 2 * H + c0 + j); \
        } } while (0)

    PF_XG(0);

    for (int t = 0; t < 512; t++) {
        float acc[3][4];
#pragma unroll
        for (int nf = 0; nf < 3; nf++)
#pragma unroll
            for (int k = 0; k < 4; k++) acc[nf][k] = 0.f;

        if (t > 0) {
            const unsigned* hsrc = g_h[t & 1];
            uint4 pre[PFN];
#pragma unroll
            for (int i = 0; i < PFN; i++) {
                int u = tid + i * 256;
                int row = u / CG, cg = u % CG;
                pre[i] = __ldcg(reinterpret_cast<const uint4*>(&hsrc[row * H + cg * 4]));
            }
#pragma unroll
            for (int i = 0; i < PFN; i++) {
                int u = tid + i * 256;
                int row = u / CG, cg = u % CG;
                *reinterpret_cast<uint4*>(&As[row * ASTR + cg * 4]) = pre[i];
            }

            for (int ch = 0; ch < NCH; ch++) {
                __syncthreads();
                if (ch + 1 < NCH) {
                    const int kc = (ch + 1) * KCH;
#pragma unroll
                    for (int i = 0; i < PFN; i++) {
                        int u = tid + i * 256;
                        int row = u / CG, cg = u % CG;
                        pre[i] = __ldcg(reinterpret_cast<const uint4*>(&hsrc[row * H + kc + cg * 4]));
                    }
                }
                const unsigned* Ab = As + (ch & 1) * (64 * ASTR);
                const int kc = ch * KCH;
#pragma unroll
                for (int k8 = 0; k8 < KCH / 8; k8++) {
                    const int kb = k8 * 8;
                    unsigned a[4], bb[3][2];
                    a[0] = Ab[rb * ASTR + kb + r4];
                    a[1] = Ab[(rb + 8) * ASTR + kb + r4];
                    a[2] = Ab[rb * ASTR + kb + r4 + 4];
                    a[3] = Ab[(rb + 8) * ASTR + kb + r4 + 4];
#pragma unroll
                    for (int nf = 0; nf < 3; nf++) {
                        int cb = wn + nf * 8 + q;
                        bb[nf][0] = Ws[cb * WSP + kc + kb + r4];
                        bb[nf][1] = Ws[cb * WSP + kc + kb + r4 + 4];
                    }
#pragma unroll
                    for (int nf = 0; nf < 3; nf++)
                        mma8(acc[nf], a, bb[nf]);
                }
                if (ch + 1 < NCH) {
                    unsigned* Bb = As + ((ch + 1) & 1) * (64 * ASTR);
#pragma unroll
                    for (int i = 0; i < PFN; i++) {
                        int u = tid + i * 256;
                        int row = u / CG, cg = u % CG;
                        *reinterpret_cast<uint4*>(&Bb[row * ASTR + cg * 4]) = pre[i];
                    }
                }
            }
        }
        // accumulators -> hg slice in SMEM
#pragma unroll
        for (int nf = 0; nf < 3; nf++) {
            int row = wm + q;
            int col = wn + nf * 8 + 2 * r4;
            hgS[row * 52 + col]           = acc[nf][0];
            hgS[row * 52 + col + 1]       = acc[nf][1];
            hgS[(row + 8) * 52 + col]     = acc[nf][2];
            hgS[(row + 8) * 52 + col + 1] = acc[nf][3];
        }
        __syncthreads();

        // ---- gate epilogue: 64 batches x 16 cols / 256 threads (round-3 blessed) ----
        unsigned* hdst = g_h[(t + 1) & 1];
#pragma unroll
        for (int it = 0; it < 4; it++) {
            int bb = bbase + it * 16;
            float hr = hgS[bb * 52 + j];
            float hz = hgS[bb * 52 + 16 + j];
            float hn = hgS[bb * 52 + 32 + j];
            float r = 1.f / (1.f + __expf(-(pxr[it] + hr)));
            float z = 1.f / (1.f + __expf(-(pxz[it] + hz)));
            float n = tanhf(pxn[it] + r * hn);
            float hnew = (1.f - z) * n + z * hl[it];
            hl[it] = hnew;
            size_t m = (size_t)bb * 512 + t;
            y[m * (size_t)H + c0 + j] = hnew;
            __stcg(&hdst[bb * H + c0 + j], f2tf(hnew));
            float s = hnew, qq = hnew * hnew;
#pragma unroll
            for (int o = 8; o > 0; o >>= 1) {
                s  += __shfl_down_sync(0xffffffffu, s, o, 16);
                qq += __shfl_down_sync(0xffffffffu, qq, o, 16);
            }
            if (j == 0) {
                __stcg(&g_psum[(size_t)cta * 32768 + m], s);
                __stcg(&g_psqs[(size_t)cta * 32768 + m], qq);
            }
        }

        if (t < 511) {
            PF_XG(t + 1);                  // independent of h; hides under barrier
            __syncthreads();               // h stores + hgS reads complete
            if (tid == 0)
                asm volatile("st.release.gpu.u32 [%0], %1;"
                             :: "l"(&g_arr[cta * 32]), "r"((unsigned)(t + 1)) : "memory");
            if (tid < NC) {
                unsigned v;
                do {
                    asm volatile("ld.acquire.gpu.u32 %0, [%1];"
                                 : "=r"(v) : "l"(&g_arr[tid * 32]) : "memory");
                } while (v < (unsigned)(t + 1));
            } else if (wid >= 4 && t >= 1) {
                // shadow: reduce LN partials of step t-1 while pollers spin
                int r = cta + (wid - 4) * NC;
                if (r < 64) {
                    int m = r * 512 + (t - 1);
                    float s = 0.f, qv = 0.f;
                    for (int c = lane; c < NC; c += 32) {
                        s  += __ldcg(&g_psum[(size_t)c * 32768 + m]);
                        qv += __ldcg(&g_psqs[(size_t)c * 32768 + m]);
                    }
#pragma unroll
                    for (int o = 16; o > 0; o >>= 1) {
                        s  += __shfl_xor_sync(0xffffffffu, s, o);
                        qv += __shfl_xor_sync(0xffffffffu, qv, o);
                    }
                    if (lane == 0) { __stcg(&g_sum[m], s); __stcg(&g_sqs[m], qv); }
                }
            }
            __syncthreads();
        }
    }
#undef PF_XG
}

// ---------------- final LayerNorm (H=128, eps=0) ----------------
template<int H>
__global__ void __launch_bounds__(128) ln_k(const float* __restrict__ gw,
                                            const float* __restrict__ bw,
                                            float* __restrict__ outp) {
    constexpr int PER = H / 128;
    __shared__ float red[8];
    const int row = blockIdx.x, tid = threadIdx.x;
    const float* p = g_actB + (size_t)row * H;
    float v[PER];
    float s = 0.f;
#pragma unroll
    for (int i = 0; i < PER; i++) { v[i] = p[tid + i * 128]; s += v[i]; }
#pragma unroll
    for (int o = 16; o > 0; o >>= 1) s += __shfl_xor_sync(0xffffffffu, s, o);
    if ((tid & 31) == 0) red[tid >> 5] = s;
    __syncthreads();
    float mean = (red[0] + red[1] + red[2] + red[3]) * (1.f / H);
    float s2 = 0.f;
#pragma unroll
    for (int i = 0; i < PER; i++) { float d = v[i] - mean; s2 += d * d; }
#pragma unroll
    for (int o = 16; o > 0; o >>= 1) s2 += __shfl_xor_sync(0xffffffffu, s2, o);
    if ((tid & 31) == 0) red[4 + (tid >> 5)] = s2;
    __syncthreads();
    float var = (red[4] + red[5] + red[6] + red[7]) * (1.f / H);
    float inv = rsqrtf(var);
#pragma unroll
    for (int i = 0; i < PER; i++) {
        int c = tid + i * 128;
        outp[(size_t)row * H + c] = (v[i] - mean) * inv * gw[c] + bw[c];
    }
}

// ---------------- driver ----------------
template<int H, int KCH>
static void launch_rec(const float* Whh) {
    constexpr int SM = sizeof(unsigned) * (48 * (H + 4) + 2 * 64 * (KCH + 4))
                     + sizeof(float) * (64 * 52);
    cudaFuncSetAttribute(gru_rec<H, KCH>, cudaFuncAttributeMaxDynamicSharedMemorySize, SM);
    gru_rec<H, KCH><<<H / 16, 256, SM>>>(Whh);
}

extern "C" void kernel_launch(void* const* d_in, const int* in_sizes, int n_in,
                              void* d_out, int out_size) {
    (void)in_sizes; (void)n_in; (void)out_size;
    const float* x = (const float*)d_in[0];
    const float* Wih[6]; const float* Whh[6]; const float* gw[6]; const float* bw[6];
    for (int l = 0; l < 6; l++) {
        Wih[l] = (const float*)d_in[1 + 4 * l];
        Whh[l] = (const float*)d_in[2 + 4 * l];
        gw[l]  = (const float*)d_in[3 + 4 * l];
        bw[l]  = (const float*)d_in[4 + 4 * l];
    }
    float* actB;
    cudaGetSymbolAddress((void**)&actB, g_actB);

    static const int DIN[6] = {128, 256, 512, 1024, 512, 256};
    static const int HH[6]  = {256, 512, 1024, 512, 256, 128};

    for (int l = 0; l < 6; l++) {
        const int K = DIN[l], H = HH[l], N = 3 * H;
        const float* A = (l == 0) ? x : (const float*)actB;
        const float* gma = (l == 0) ? nullptr : gw[l - 1];
        const float* bta = (l == 0) ? nullptr : bw[l - 1];
        const int nprev = (l == 0) ? 0 : HH[l - 1] / 16;
        dim3 grid(N / 64, 256);
        if (l == 0) {
            gemm_xg<128, false><<<grid, 256>>>(A, Wih[l], N, gma, bta, nprev);
        } else {
            switch (K) {
                case 256:  gemm_xg<256, true><<<grid, 256>>>(A, Wih[l], N, gma, bta, nprev); break;
                case 512:  gemm_xg<512, true><<<grid, 256>>>(A, Wih[l], N, gma, bta, nprev); break;
                case 1024: gemm_xg<1024, true><<<grid, 256>>>(A, Wih[l], N, gma, bta, nprev); break;
            }
        }
        switch (H) {
            case 128:  launch_rec<128, 64>(Whh[l]); break;
            case 256:  launch_rec<256, 64>(Whh[l]); break;
            case 512:  launch_rec<512, 64>(Whh[l]); break;
            case 1024: launch_rec<1024, 32>(Whh[l]); break;
        }
    }
    ln_k<128><<<32768, 128>>>(gw[5], bw[5], (float*)d_out);
}

// round 8
// speedup vs baseline: 1.9501x; 1.2901x over previous
#include <cuda_runtime.h>
#include <cstdint>

// ---------------- static scratch (no allocs allowed) ----------------
__device__ float g_xg[32768 * 3072];        // input-projection buffer (max 3H=3072)
__device__ float g_actB[32768 * 1024];      // raw GRU outputs (pre-LN)
__device__ unsigned g_h[2][64 * 1024];      // double-buffered hidden state (tf32 bits)
__device__ float g_psum[128 * 32768];       // per-CTA partial row sums
__device__ float g_psqs[128 * 32768];       // per-CTA partial row sumsq
__device__ float g_sum[32768];              // reduced row sums
__device__ float g_sqs[32768];              // reduced row sumsq
__device__ unsigned g_arr[128 * 32];        // decentralized barrier slots (128B stride)

// ---------------- helpers ----------------
__device__ __forceinline__ unsigned f2tf(float x) {
    unsigned r; asm("cvt.rna.tf32.f32 %0, %1;" : "=r"(r) : "f"(x)); return r;
}
__device__ __forceinline__ void mma8(float* c, const unsigned* a, const unsigned* b) {
    asm volatile("mma.sync.aligned.m16n8k8.row.col.f32.tf32.tf32.f32 "
                 "{%0,%1,%2,%3}, {%4,%5,%6,%7}, {%8,%9}, {%0,%1,%2,%3};"
                 : "+f"(c[0]), "+f"(c[1]), "+f"(c[2]), "+f"(c[3])
                 : "r"(a[0]), "r"(a[1]), "r"(a[2]), "r"(a[3]),
                   "r"(b[0]), "r"(b[1]));
}

// ---------------- input-projection GEMM with optional fused LN ----------------
template<int K, bool LN>
__global__ void __launch_bounds__(256) gemm_xg(const float* __restrict__ A,
                                               const float* __restrict__ W,
                                               int N,
                                               const float* __restrict__ gma,
                                               const float* __restrict__ bta,
                                               int nprev) {
    __shared__ unsigned As[128 * 36];
    __shared__ unsigned Bs[64 * 36];
    __shared__ float gS[K], bS[K];
    __shared__ float rmS[128], rsS[128];

    const int m0 = blockIdx.y * 128;
    const int n0 = blockIdx.x * 64;
    const int tid = threadIdx.x;
    const int lane = tid & 31, wid = tid >> 5;
    const int wm = (wid & 3) * 32, wn = (wid >> 2) * 32;

    if (blockIdx.x == 0 && blockIdx.y == 0 && tid < 128)
        g_arr[tid * 32] = 0u;              // reset barrier slots for the next rec

    if (LN) {
        for (int i = tid; i < K; i += 256) { gS[i] = gma[i]; bS[i] = bta[i]; }
        if (tid < 128) {
            int m = m0 + tid;
            float s, q;
            if ((m & 511) >= 510) {
                s = 0.f; q = 0.f;
                for (int c = 0; c < nprev; c++) {
                    s += g_psum[(size_t)c * 32768 + m];
                    q += g_psqs[(size_t)c * 32768 + m];
                }
            } else {
                s = g_sum[m]; q = g_sqs[m];
            }
            float mean = s * (1.f / K);
            float var = q * (1.f / K) - mean * mean;
            rmS[tid] = mean;
            rsS[tid] = rsqrtf(var);
        }
        __syncthreads();
    }

    float acc[2][4][4];
#pragma unroll
    for (int i = 0; i < 2; i++)
#pragma unroll
        for (int j = 0; j < 4; j++)
#pragma unroll
            for (int k = 0; k < 4; k++) acc[i][j][k] = 0.f;

    const int lr = tid >> 3;
    const int lc = (tid & 7) * 4;

    for (int kc = 0; kc < K; kc += 32) {
#pragma unroll
        for (int i = 0; i < 4; i++) {
            int r = lr + i * 32;
            float4 v = *reinterpret_cast<const float4*>(&A[(size_t)(m0 + r) * K + kc + lc]);
            if (LN) {
                float mm = rmS[r], ss = rsS[r];
                int k = kc + lc;
                v.x = (v.x - mm) * ss * gS[k]     + bS[k];
                v.y = (v.y - mm) * ss * gS[k + 1] + bS[k + 1];
                v.z = (v.z - mm) * ss * gS[k + 2] + bS[k + 2];
                v.w = (v.w - mm) * ss * gS[k + 3] + bS[k + 3];
            }
            As[r * 36 + lc + 0] = f2tf(v.x); As[r * 36 + lc + 1] = f2tf(v.y);
            As[r * 36 + lc + 2] = f2tf(v.z); As[r * 36 + lc + 3] = f2tf(v.w);
        }
#pragma unroll
        for (int i = 0; i < 2; i++) {
            int r = lr + i * 32;
            float4 v = *reinterpret_cast<const float4*>(&W[(size_t)(n0 + r) * K + kc + lc]);
            Bs[r * 36 + lc + 0] = f2tf(v.x); Bs[r * 36 + lc + 1] = f2tf(v.y);
            Bs[r * 36 + lc + 2] = f2tf(v.z); Bs[r * 36 + lc + 3] = f2tf(v.w);
        }
        __syncthreads();
#pragma unroll
        for (int k8 = 0; k8 < 4; k8++) {
            const int kb = k8 * 8;
            unsigned a[2][4], b[4][2];
#pragma unroll
            for (int mf = 0; mf < 2; mf++) {
                int rb = wm + mf * 16 + (lane >> 2);
                a[mf][0] = As[rb * 36 + kb + (lane & 3)];
                a[mf][1] = As[(rb + 8) * 36 + kb + (lane & 3)];
                a[mf][2] = As[rb * 36 + kb + (lane & 3) + 4];
                a[mf][3] = As[(rb + 8) * 36 + kb + (lane & 3) + 4];
            }
#pragma unroll
            for (int nf = 0; nf < 4; nf++) {
                int cb = wn + nf * 8 + (lane >> 2);
                b[nf][0] = Bs[cb * 36 + kb + (lane & 3)];
                b[nf][1] = Bs[cb * 36 + kb + (lane & 3) + 4];
            }
#pragma unroll
            for (int mf = 0; mf < 2; mf++)
#pragma unroll
                for (int nf = 0; nf < 4; nf++)
                    mma8(acc[mf][nf], a[mf], b[nf]);
        }
        __syncthreads();
    }
#pragma unroll
    for (int mf = 0; mf < 2; mf++)
#pragma unroll
        for (int nf = 0; nf < 4; nf++) {
            int row = m0 + wm + mf * 16 + (lane >> 2);
            int col = n0 + wn + nf * 8 + 2 * (lane & 3);
            g_xg[(size_t)row * N + col]     = acc[mf][nf][0];
            g_xg[(size_t)row * N + col + 1] = acc[mf][nf][1];
            g_xg[(size_t)(row + 8) * N + col]     = acc[mf][nf][2];
            g_xg[(size_t)(row + 8) * N + col + 1] = acc[mf][nf][3];
        }
}

// ---------------- persistent GRU recurrence ----------------
// grid = H/8 CTAs (co-resident), 256 threads, 8 warps: 4 m-tiles x 2-way K split.
// Each CTA owns 8 h-cols; 24xH Whh slice in SMEM, stored in FRAGMENT-PACKED order
// so each B-frag is one conflict-free LDS.64. A staged per 64-wide chunk,
// register-double-buffered. g_h double-buffered (race-free with the barrier).
// Cross-warp K merge through hgS. Decentralized barrier + shadow LN reduction.
template<int H>
__global__ void __launch_bounds__(256, 1) gru_rec(const float* __restrict__ Whh) {
    constexpr int KCH  = 64;
    constexpr int ASTR = KCH + 4;
    constexpr int NCH  = H / KCH;
    constexpr int NC   = H / 8;          // == gridDim.x  (<= 128)
    extern __shared__ unsigned char smem_raw[];
    unsigned* Wf = reinterpret_cast<unsigned*>(smem_raw);      // [H/8][3][64] packed B
    unsigned* As = Wf + (H / 8) * 192;                         // 2 x [64][ASTR]
    float* hgS = reinterpret_cast<float*>(As + 2 * 64 * ASTR); // [64][40]

    const float* xg = g_xg;
    float* y = g_actB;
    const int tid = threadIdx.x;
    const int lane = tid & 31, wid = tid >> 5;
    const int cta = blockIdx.x;
    const int c0 = cta * 8;
    const int q = lane >> 2, r4 = lane & 3;
    const int rb = (wid & 3) * 16 + q;   // m-tile row base
    const int kg0 = (wid >> 2) * 32;     // k-half within chunk: warps0-3 -> 0, 4-7 -> 32

    // one-time: Whh slice -> SMEM in fragment-packed tf32 order.
    // B-frag read:  word ((kb8*3)+gate)*64 + (j*4+r4)*2 + half  == W[gate*8+j][kb8*8+r4+4*half]
    {
        constexpr int nf4 = H / 4;
        for (int idx = tid; idx < 24 * nf4; idx += 256) {
            int nn = idx / nf4;               // 0..23 : gate*8 + j
            int c4 = (idx % nf4) * 4;         // k, multiple of 4
            int gate = nn >> 3, j = nn & 7;
            float4 v = *reinterpret_cast<const float4*>(&Whh[(size_t)(gate * H + c0 + j) * H + c4]);
            int kb8 = c4 >> 3;
            int half = (c4 >> 2) & 1;
            unsigned* base = Wf + (kb8 * 3 + gate) * 64 + j * 8 + half;
            base[0] = f2tf(v.x); base[2] = f2tf(v.y);
            base[4] = f2tf(v.z); base[6] = f2tf(v.w);
        }
    }
    __syncthreads();

    const int col = tid & 7;             // epilogue: own column
    const int brow = tid >> 3;           // epilogue: batch rows brow, brow+32
    float hl[2] = {0.f, 0.f};
    float pxr[2], pxz[2], pxn[2];

#define PF_XG(TT) do { \
        _Pragma("unroll") \
        for (int it = 0; it < 2; it++) { \
            int b_ = brow + it * 32; \
            const float* xrow = xg + ((size_t)b_ * 512 + (TT)) * (size_t)(3 * H); \
            pxr[it] = __ldcs(xrow + c0 + col); \
            pxz[it] = __ldcs(xrow + H + c0 + col); \
            pxn[it] = __ldcs(xrow + 2 * H + c0 + col); \
        } } while (0)

    PF_XG(0);

    // staging map: 64 rows x 16 col-groups of uint4; 4 per thread, fixed cg = tid&15
    const int sgr = tid >> 4;            // base row (adds i*16)
    const int sgc = (tid & 15) * 4;      // col offset (words)

    for (int t = 0; t < 512; t++) {
        float acc[3][4];
#pragma unroll
        for (int nf = 0; nf < 3; nf++)
#pragma unroll
            for (int k = 0; k < 4; k++) acc[nf][k] = 0.f;

        if (t > 0) {
            const unsigned* hsrc = g_h[t & 1];
            uint4 pre[4];
#pragma unroll
            for (int i = 0; i < 4; i++)
                pre[i] = __ldcg(reinterpret_cast<const uint4*>(&hsrc[(sgr + i * 16) * H + sgc]));
#pragma unroll
            for (int i = 0; i < 4; i++)
                *reinterpret_cast<uint4*>(&As[(sgr + i * 16) * ASTR + sgc]) = pre[i];

            for (int ch = 0; ch < NCH; ch++) {
                __syncthreads();
                if (ch + 1 < NCH) {
                    const int kc = (ch + 1) * KCH;
#pragma unroll
                    for (int i = 0; i < 4; i++)
                        pre[i] = __ldcg(reinterpret_cast<const uint4*>(&hsrc[(sgr + i * 16) * H + kc + sgc]));
                }
                const unsigned* Ab = As + (ch & 1) * (64 * ASTR);
#pragma unroll
                for (int k8 = 0; k8 < 4; k8++) {
                    const int kbl = kg0 + k8 * 8;                 // local k in chunk
                    const int g8 = ch * 8 + (kg0 >> 3) + k8;      // global k8 index
                    unsigned a[4];
                    a[0] = Ab[rb * ASTR + kbl + r4];
                    a[1] = Ab[(rb + 8) * ASTR + kbl + r4];
                    a[2] = Ab[rb * ASTR + kbl + r4 + 4];
                    a[3] = Ab[(rb + 8) * ASTR + kbl + r4 + 4];
#pragma unroll
                    for (int nf = 0; nf < 3; nf++) {
                        uint2 bb = *reinterpret_cast<const uint2*>(&Wf[(g8 * 3 + nf) * 64 + lane * 2]);
                        unsigned bfr[2] = {bb.x, bb.y};
                        mma8(acc[nf], a, bfr);
                    }
                }
                if (ch + 1 < NCH) {
                    unsigned* Bb = As + ((ch + 1) & 1) * (64 * ASTR);
#pragma unroll
                    for (int i = 0; i < 4; i++)
                        *reinterpret_cast<uint4*>(&Bb[(sgr + i * 16) * ASTR + sgc]) = pre[i];
                }
            }
        }
        // ---- cross-warp K merge: warps 4-7 store, warps 0-3 add ----
        if (wid >= 4) {
#pragma unroll
            for (int nf = 0; nf < 3; nf++) {
                int row = (wid & 3) * 16 + q;
                int cc = nf * 8 + 2 * r4;
                hgS[row * 40 + cc]           = acc[nf][0];
                hgS[row * 40 + cc + 1]       = acc[nf][1];
                hgS[(row + 8) * 40 + cc]     = acc[nf][2];
                hgS[(row + 8) * 40 + cc + 1] = acc[nf][3];
            }
        }
        __syncthreads();
        if (wid < 4) {
#pragma unroll
            for (int nf = 0; nf < 3; nf++) {
                int row = (wid & 3) * 16 + q;
                int cc = nf * 8 + 2 * r4;
                hgS[row * 40 + cc]           += acc[nf][0];
                hgS[row * 40 + cc + 1]       += acc[nf][1];
                hgS[(row + 8) * 40 + cc]     += acc[nf][2];
                hgS[(row + 8) * 40 + cc + 1] += acc[nf][3];
            }
        }
        __syncthreads();

        // ---- gate epilogue: all 256 threads, 2 (batch,col) items each ----
        unsigned* hdst = g_h[(t + 1) & 1];
#pragma unroll
        for (int it = 0; it < 2; it++) {
            int b = brow + it * 32;
            float hr = hgS[b * 40 + col];
            float hz = hgS[b * 40 + 8 + col];
            float hn = hgS[b * 40 + 16 + col];
            float r = 1.f / (1.f + __expf(-(pxr[it] + hr)));
            float z = 1.f / (1.f + __expf(-(pxz[it] + hz)));
            float n = tanhf(pxn[it] + r * hn);
            float h2 = (1.f - z) * n + z * hl[it];
            hl[it] = h2;
            size_t m = (size_t)b * 512 + t;
            y[m * (size_t)H + c0 + col] = h2;
            __stcg(&hdst[b * H + c0 + col], f2tf(h2));
            float s = h2, qq = h2 * h2;
#pragma unroll
            for (int o = 4; o > 0; o >>= 1) {
                s  += __shfl_down_sync(0xffffffffu, s, o, 8);
                qq += __shfl_down_sync(0xffffffffu, qq, o, 8);
            }
            if (col == 0) {
                __stcg(&g_psum[(size_t)cta * 32768 + m], s);
                __stcg(&g_psqs[(size_t)cta * 32768 + m], qq);
            }
        }

        if (t < 511) {
            PF_XG(t + 1);                  // independent of h; hides under barrier
            __syncthreads();               // h stores + hgS reads complete
            if (tid == 0)
                asm volatile("st.release.gpu.u32 [%0], %1;"
                             :: "l"(&g_arr[cta * 32]), "r"((unsigned)(t + 1)) : "memory");
            if (tid < NC) {
                unsigned v;
                do {
                    asm volatile("ld.acquire.gpu.u32 %0, [%1];"
                                 : "=r"(v) : "l"(&g_arr[tid * 32]) : "memory");
                } while (v < (unsigned)(t + 1));
            } else if (wid >= 4 && t >= 1) {
                // shadow: reduce LN partials of step t-1 while pollers spin
                int r = cta + (wid - 4) * NC;
                if (r < 64) {
                    int m = r * 512 + (t - 1);
                    float s = 0.f, qv = 0.f;
                    for (int c = lane; c < NC; c += 32) {
                        s  += __ldcg(&g_psum[(size_t)c * 32768 + m]);
                        qv += __ldcg(&g_psqs[(size_t)c * 32768 + m]);
                    }
#pragma unroll
                    for (int o = 16; o > 0; o >>= 1) {
                        s  += __shfl_xor_sync(0xffffffffu, s, o);
                        qv += __shfl_xor_sync(0xffffffffu, qv, o);
                    }
                    if (lane == 0) { __stcg(&g_sum[m], s); __stcg(&g_sqs[m], qv); }
                }
            }
            __syncthreads();
        }
    }
#undef PF_XG
}

// ---------------- final LayerNorm (H=128, eps=0) ----------------
template<int H>
__global__ void __launch_bounds__(128) ln_k(const float* __restrict__ gw,
                                            const float* __restrict__ bw,
                                            float* __restrict__ outp) {
    constexpr int PER = H / 128;
    __shared__ float red[8];
    const int row = blockIdx.x, tid = threadIdx.x;
    const float* p = g_actB + (size_t)row * H;
    float v[PER];
    float s = 0.f;
#pragma unroll
    for (int i = 0; i < PER; i++) { v[i] = p[tid + i * 128]; s += v[i]; }
#pragma unroll
    for (int o = 16; o > 0; o >>= 1) s += __shfl_xor_sync(0xffffffffu, s, o);
    if ((tid & 31) == 0) red[tid >> 5] = s;
    __syncthreads();
    float mean = (red[0] + red[1] + red[2] + red[3]) * (1.f / H);
    float s2 = 0.f;
#pragma unroll
    for (int i = 0; i < PER; i++) { float d = v[i] - mean; s2 += d * d; }
#pragma unroll
    for (int o = 16; o > 0; o >>= 1) s2 += __shfl_xor_sync(0xffffffffu, s2, o);
    if ((tid & 31) == 0) red[4 + (tid >> 5)] = s2;
    __syncthreads();
    float var = (red[4] + red[5] + red[6] + red[7]) * (1.f / H);
    float inv = rsqrtf(var);
#pragma unroll
    for (int i = 0; i < PER; i++) {
        int c = tid + i * 128;
        outp[(size_t)row * H + c] = (v[i] - mean) * inv * gw[c] + bw[c];
    }
}

// ---------------- driver ----------------
template<int H>
static void launch_rec(const float* Whh) {
    constexpr int SM = sizeof(unsigned) * ((H / 8) * 192 + 2 * 64 * 68)
                     + sizeof(float) * (64 * 40);
    cudaFuncSetAttribute(gru_rec<H>, cudaFuncAttributeMaxDynamicSharedMemorySize, SM);
    gru_rec<H><<<H / 8, 256, SM>>>(Whh);
}

extern "C" void kernel_launch(void* const* d_in, const int* in_sizes, int n_in,
                              void* d_out, int out_size) {
    (void)in_sizes; (void)n_in; (void)out_size;
    const float* x = (const float*)d_in[0];
    const float* Wih[6]; const float* Whh[6]; const float* gw[6]; const float* bw[6];
    for (int l = 0; l < 6; l++) {
        Wih[l] = (const float*)d_in[1 + 4 * l];
        Whh[l] = (const float*)d_in[2 + 4 * l];
        gw[l]  = (const float*)d_in[3 + 4 * l];
        bw[l]  = (const float*)d_in[4 + 4 * l];
    }
    float* actB;
    cudaGetSymbolAddress((void**)&actB, g_actB);

    static const int DIN[6] = {128, 256, 512, 1024, 512, 256};
    static const int HH[6]  = {256, 512, 1024, 512, 256, 128};

    for (int l = 0; l < 6; l++) {
        const int K = DIN[l], H = HH[l], N = 3 * H;
        const float* A = (l == 0) ? x : (const float*)actB;
        const float* gma = (l == 0) ? nullptr : gw[l - 1];
        const float* bta = (l == 0) ? nullptr : bw[l - 1];
        const int nprev = (l == 0) ? 0 : HH[l - 1] / 8;
        dim3 grid(N / 64, 256);
        if (l == 0) {
            gemm_xg<128, false><<<grid, 256>>>(A, Wih[l], N, gma, bta, nprev);
        } else {
            switch (K) {
                case 256:  gemm_xg<256, true><<<grid, 256>>>(A, Wih[l], N, gma, bta, nprev); break;
                case 512:  gemm_xg<512, true><<<grid, 256>>>(A, Wih[l], N, gma, bta, nprev); break;
                case 1024: gemm_xg<1024, true><<<grid, 256>>>(A, Wih[l], N, gma, bta, nprev); break;
            }
        }
        switch (H) {
            case 128:  launch_rec<128>(Whh[l]); break;
            case 256:  launch_rec<256>(Whh[l]); break;
            case 512:  launch_rec<512>(Whh[l]); break;
            case 1024: launch_rec<1024>(Whh[l]); break;
        }
    }
    ln_k<128><<<32768, 128>>>(gw[5], bw[5], (float*)d_out);
}

// round 9
// speedup vs baseline: 2.0286x; 1.0402x over previous
#include <cuda_runtime.h>
#include <cstdint>

// ---------------- static scratch (no allocs allowed) ----------------
__device__ float g_xg[32768 * 3072];        // input-projection buffer (max 3H=3072)
__device__ float g_actB[32768 * 1024];      // raw GRU outputs (pre-LN)
__device__ unsigned g_h[2][64 * 1024];      // double-buffered hidden state (tf32 bits)
__device__ float g_psum[128 * 32768];       // per-CTA partial row sums
__device__ float g_psqs[128 * 32768];       // per-CTA partial row sumsq
__device__ float g_sum[32768];              // reduced row sums
__device__ float g_sqs[32768];              // reduced row sumsq
__device__ unsigned g_arr[128 * 32];        // decentralized barrier slots (128B stride)

// ---------------- helpers ----------------
__device__ __forceinline__ unsigned f2tf(float x) {
    unsigned r; asm("cvt.rna.tf32.f32 %0, %1;" : "=r"(r) : "f"(x)); return r;
}
__device__ __forceinline__ void mma8(float* c, const unsigned* a, const unsigned* b) {
    asm volatile("mma.sync.aligned.m16n8k8.row.col.f32.tf32.tf32.f32 "
                 "{%0,%1,%2,%3}, {%4,%5,%6,%7}, {%8,%9}, {%0,%1,%2,%3};"
                 : "+f"(c[0]), "+f"(c[1]), "+f"(c[2]), "+f"(c[3])
                 : "r"(a[0]), "r"(a[1]), "r"(a[2]), "r"(a[3]),
                   "r"(b[0]), "r"(b[1]));
}

// ---------------- input-projection GEMM with optional fused LN ----------------
template<int K, bool LN>
__global__ void __launch_bounds__(256) gemm_xg(const float* __restrict__ A,
                                               const float* __restrict__ W,
                                               int N,
                                               const float* __restrict__ gma,
                                               const float* __restrict__ bta,
                                               int nprev) {
    __shared__ unsigned As[128 * 36];
    __shared__ unsigned Bs[64 * 36];
    __shared__ float gS[K], bS[K];
    __shared__ float rmS[128], rsS[128];

    const int m0 = blockIdx.y * 128;
    const int n0 = blockIdx.x * 64;
    const int tid = threadIdx.x;
    const int lane = tid & 31, wid = tid >> 5;
    const int wm = (wid & 3) * 32, wn = (wid >> 2) * 32;

    if (blockIdx.x == 0 && blockIdx.y == 0 && tid < 128)
        g_arr[tid * 32] = 0u;              // reset barrier slots for the next rec

    if (LN) {
        for (int i = tid; i < K; i += 256) { gS[i] = gma[i]; bS[i] = bta[i]; }
        if (tid < 128) {
            int m = m0 + tid;
            float s, q;
            if ((m & 511) >= 510) {
                s = 0.f; q = 0.f;
                for (int c = 0; c < nprev; c++) {
                    s += g_psum[(size_t)c * 32768 + m];
                    q += g_psqs[(size_t)c * 32768 + m];
                }
            } else {
                s = g_sum[m]; q = g_sqs[m];
            }
            float mean = s * (1.f / K);
            float var = q * (1.f / K) - mean * mean;
            rmS[tid] = mean;
            rsS[tid] = rsqrtf(var);
        }
        __syncthreads();
    }

    float acc[2][4][4];
#pragma unroll
    for (int i = 0; i < 2; i++)
#pragma unroll
        for (int j = 0; j < 4; j++)
#pragma unroll
            for (int k = 0; k < 4; k++) acc[i][j][k] = 0.f;

    const int lr = tid >> 3;
    const int lc = (tid & 7) * 4;

    for (int kc = 0; kc < K; kc += 32) {
#pragma unroll
        for (int i = 0; i < 4; i++) {
            int r = lr + i * 32;
            float4 v = *reinterpret_cast<const float4*>(&A[(size_t)(m0 + r) * K + kc + lc]);
            if (LN) {
                float mm = rmS[r], ss = rsS[r];
                int k = kc + lc;
                v.x = (v.x - mm) * ss * gS[k]     + bS[k];
                v.y = (v.y - mm) * ss * gS[k + 1] + bS[k + 1];
                v.z = (v.z - mm) * ss * gS[k + 2] + bS[k + 2];
                v.w = (v.w - mm) * ss * gS[k + 3] + bS[k + 3];
            }
            As[r * 36 + lc + 0] = f2tf(v.x); As[r * 36 + lc + 1] = f2tf(v.y);
            As[r * 36 + lc + 2] = f2tf(v.z); As[r * 36 + lc + 3] = f2tf(v.w);
        }
#pragma unroll
        for (int i = 0; i < 2; i++) {
            int r = lr + i * 32;
            float4 v = *reinterpret_cast<const float4*>(&W[(size_t)(n0 + r) * K + kc + lc]);
            Bs[r * 36 + lc + 0] = f2tf(v.x); Bs[r * 36 + lc + 1] = f2tf(v.y);
            Bs[r * 36 + lc + 2] = f2tf(v.z); Bs[r * 36 + lc + 3] = f2tf(v.w);
        }
        __syncthreads();
#pragma unroll
        for (int k8 = 0; k8 < 4; k8++) {
            const int kb = k8 * 8;
            unsigned a[2][4], b[4][2];
#pragma unroll
            for (int mf = 0; mf < 2; mf++) {
                int rb = wm + mf * 16 + (lane >> 2);
                a[mf][0] = As[rb * 36 + kb + (lane & 3)];
                a[mf][1] = As[(rb + 8) * 36 + kb + (lane & 3)];
                a[mf][2] = As[rb * 36 + kb + (lane & 3) + 4];
                a[mf][3] = As[(rb + 8) * 36 + kb + (lane & 3) + 4];
            }
#pragma unroll
            for (int nf = 0; nf < 4; nf++) {
                int cb = wn + nf * 8 + (lane >> 2);
                b[nf][0] = Bs[cb * 36 + kb + (lane & 3)];
                b[nf][1] = Bs[cb * 36 + kb + (lane & 3) + 4];
            }
#pragma unroll
            for (int mf = 0; mf < 2; mf++)
#pragma unroll
                for (int nf = 0; nf < 4; nf++)
                    mma8(acc[mf][nf], a[mf], b[nf]);
        }
        __syncthreads();
    }
#pragma unroll
    for (int mf = 0; mf < 2; mf++)
#pragma unroll
        for (int nf = 0; nf < 4; nf++) {
            int row = m0 + wm + mf * 16 + (lane >> 2);
            int col = n0 + wn + nf * 8 + 2 * (lane & 3);
            g_xg[(size_t)row * N + col]     = acc[mf][nf][0];
            g_xg[(size_t)row * N + col + 1] = acc[mf][nf][1];
            g_xg[(size_t)(row + 8) * N + col]     = acc[mf][nf][2];
            g_xg[(size_t)(row + 8) * N + col + 1] = acc[mf][nf][3];
        }
}

// ---------------- persistent GRU recurrence ----------------
// grid = H/8 CTAs, 256 threads, 8 warps: 2 m-tiles (32 rows) x 4-way K split.
// Warp (mi = wid&1, kq = wid>>1). Each CTA owns 8 h-cols; 24xH Whh slice in SMEM
// in fragment-packed order (one conflict-free LDS.64 per B-frag). A staged per
// 128-wide chunk, register-double-buffered. 4-way K merge in one SMEM round.
// g_h double-buffered; decentralized barrier + shadow LN reduction.
template<int H>
__global__ void __launch_bounds__(256, 1) gru_rec(const float* __restrict__ Whh) {
    constexpr int KCH  = 128;
    constexpr int ASTR = KCH + 4;        // 132
    constexpr int NCH  = H / KCH;
    constexpr int NC   = H / 8;          // == gridDim.x  (<= 128)
    extern __shared__ unsigned char smem_raw[];
    unsigned* Wf = reinterpret_cast<unsigned*>(smem_raw);      // [H/8][3][64] packed B
    unsigned* As = Wf + (H / 8) * 192;                         // 2 x [64][ASTR]
    float* hgS = reinterpret_cast<float*>(As + 2 * 64 * ASTR); // 3 x [64][40]

    const float* xg = g_xg;
    float* y = g_actB;
    const int tid = threadIdx.x;
    const int lane = tid & 31, wid = tid >> 5;
    const int cta = blockIdx.x;
    const int c0 = cta * 8;
    const int q = lane >> 2, r4 = lane & 3;
    const int mi = wid & 1;              // m-half: rows mi*32..mi*32+31
    const int kq = wid >> 1;             // k-quarter within chunk

    // one-time: Whh slice -> SMEM in fragment-packed tf32 order.
    // B-frag read:  word (g8*3+gate)*64 + (j*4+r4)*2 + half == W[gate*8+j][g8*8+r4+4*half]
    {
        constexpr int nf4 = H / 4;
        for (int idx = tid; idx < 24 * nf4; idx += 256) {
            int nn = idx / nf4;               // 0..23 : gate*8 + j
            int c4 = (idx % nf4) * 4;         // k, multiple of 4
            int gate = nn >> 3, j = nn & 7;
            float4 v = *reinterpret_cast<const float4*>(&Whh[(size_t)(gate * H + c0 + j) * H + c4]);
            int kb8 = c4 >> 3;
            int half = (c4 >> 2) & 1;
            unsigned* base = Wf + (kb8 * 3 + gate) * 64 + j * 8 + half;
            base[0] = f2tf(v.x); base[2] = f2tf(v.y);
            base[4] = f2tf(v.z); base[6] = f2tf(v.w);
        }
    }
    __syncthreads();

    const int col = tid & 7;             // epilogue: own column
    const int brow = tid >> 3;           // epilogue: batch rows brow, brow+32
    float hl[2] = {0.f, 0.f};
    float pxr[2], pxz[2], pxn[2];

#define PF_XG(TT) do { \
        _Pragma("unroll") \
        for (int it = 0; it < 2; it++) { \
            int b_ = brow + it * 32; \
            const float* xrow = xg + ((size_t)b_ * 512 + (TT)) * (size_t)(3 * H); \
            pxr[it] = __ldcs(xrow + c0 + col); \
            pxz[it] = __ldcs(xrow + H + c0 + col); \
            pxn[it] = __ldcs(xrow + 2 * H + c0 + col); \
        } } while (0)

    PF_XG(0);

    // staging map: 64 rows x 32 col-groups of uint4; 8 per thread
    const int srow = tid >> 5;           // base row (adds i*8)
    const int scol = (tid & 31) * 4;     // word offset 0..124

    for (int t = 0; t < 512; t++) {
        float acc[2][3][4];
#pragma unroll
        for (int mf = 0; mf < 2; mf++)
#pragma unroll
            for (int nf = 0; nf < 3; nf++)
#pragma unroll
                for (int k = 0; k < 4; k++) acc[mf][nf][k] = 0.f;

        if (t > 0) {
            const unsigned* hsrc = g_h[t & 1];
            uint4 pre[8];
#pragma unroll
            for (int i = 0; i < 8; i++)
                pre[i] = __ldcg(reinterpret_cast<const uint4*>(&hsrc[(srow + i * 8) * H + scol]));
#pragma unroll
            for (int i = 0; i < 8; i++)
                *reinterpret_cast<uint4*>(&As[(srow + i * 8) * ASTR + scol]) = pre[i];

            for (int ch = 0; ch < NCH; ch++) {
                __syncthreads();
                if (ch + 1 < NCH) {
                    const int kc = (ch + 1) * KCH;
#pragma unroll
                    for (int i = 0; i < 8; i++)
                        pre[i] = __ldcg(reinterpret_cast<const uint4*>(&hsrc[(srow + i * 8) * H + kc + scol]));
                }
                const unsigned* Ab = As + (ch & 1) * (64 * ASTR);
#pragma unroll
                for (int k8 = 0; k8 < 4; k8++) {
                    const int kbl = kq * 32 + k8 * 8;             // local k in chunk
                    const int g8 = ch * 16 + kq * 4 + k8;         // global k8 index
                    const int rb0 = mi * 32 + q;
                    const int rb1 = mi * 32 + 16 + q;
                    unsigned a0[4], a1[4];
                    a0[0] = Ab[rb0 * ASTR + kbl + r4];
                    a0[1] = Ab[(rb0 + 8) * ASTR + kbl + r4];
                    a0[2] = Ab[rb0 * ASTR + kbl + r4 + 4];
                    a0[3] = Ab[(rb0 + 8) * ASTR + kbl + r4 + 4];
                    a1[0] = Ab[rb1 * ASTR + kbl + r4];
                    a1[1] = Ab[(rb1 + 8) * ASTR + kbl + r4];
                    a1[2] = Ab[rb1 * ASTR + kbl + r4 + 4];
                    a1[3] = Ab[(rb1 + 8) * ASTR + kbl + r4 + 4];
#pragma unroll
                    for (int nf = 0; nf < 3; nf++) {
                        uint2 bb = *reinterpret_cast<const uint2*>(&Wf[(g8 * 3 + nf) * 64 + lane * 2]);
                        unsigned bfr[2] = {bb.x, bb.y};
                        mma8(acc[0][nf], a0, bfr);
                        mma8(acc[1][nf], a1, bfr);
                    }
                }
                if (ch + 1 < NCH) {
                    unsigned* Bb = As + ((ch + 1) & 1) * (64 * ASTR);
#pragma unroll
                    for (int i = 0; i < 8; i++)
                        *reinterpret_cast<uint4*>(&Bb[(srow + i * 8) * ASTR + scol]) = pre[i];
                }
            }
        }
        // ---- 4-way K merge: kq=1..3 store to buf kq-1; kq=0 folds into buf0 ----
        if (kq > 0) {
            float* dst = hgS + (kq - 1) * (64 * 40);
#pragma unroll
            for (int mf = 0; mf < 2; mf++)
#pragma unroll
                for (int nf = 0; nf < 3; nf++) {
                    int row = mi * 32 + mf * 16 + q;
                    int cc = nf * 8 + 2 * r4;
                    dst[row * 40 + cc]           = acc[mf][nf][0];
                    dst[row * 40 + cc + 1]       = acc[mf][nf][1];
                    dst[(row + 8) * 40 + cc]     = acc[mf][nf][2];
                    dst[(row + 8) * 40 + cc + 1] = acc[mf][nf][3];
                }
        }
        __syncthreads();
        if (kq == 0) {
#pragma unroll
            for (int mf = 0; mf < 2; mf++)
#pragma unroll
                for (int nf = 0; nf < 3; nf++) {
                    int row = mi * 32 + mf * 16 + q;
                    int cc = nf * 8 + 2 * r4;
#pragma unroll
                    for (int e = 0; e < 4; e++) {
                        int rr = row + (e >> 1) * 8;
                        int cw = cc + (e & 1);
                        float v = acc[mf][nf][e]
                                + hgS[0 * 2560 + rr * 40 + cw]
                                + hgS[1 * 2560 + rr * 40 + cw]
                                + hgS[2 * 2560 + rr * 40 + cw];
                        hgS[rr * 40 + cw] = v;
                    }
                }
        }
        __syncthreads();

        // ---- gate epilogue: all 256 threads, 2 (batch,col) items each ----
        unsigned* hdst = g_h[(t + 1) & 1];
#pragma unroll
        for (int it = 0; it < 2; it++) {
            int b = brow + it * 32;
            float hr = hgS[b * 40 + col];
            float hz = hgS[b * 40 + 8 + col];
            float hn = hgS[b * 40 + 16 + col];
            float r = 1.f / (1.f + __expf(-(pxr[it] + hr)));
            float z = 1.f / (1.f + __expf(-(pxz[it] + hz)));
            float n = tanhf(pxn[it] + r * hn);
            float h2 = (1.f - z) * n + z * hl[it];
            hl[it] = h2;
            size_t m = (size_t)b * 512 + t;
            y[m * (size_t)H + c0 + col] = h2;
            __stcg(&hdst[b * H + c0 + col], f2tf(h2));
            float s = h2, qq = h2 * h2;
#pragma unroll
            for (int o = 4; o > 0; o >>= 1) {
                s  += __shfl_down_sync(0xffffffffu, s, o, 8);
                qq += __shfl_down_sync(0xffffffffu, qq, o, 8);
            }
            if (col == 0) {
                __stcg(&g_psum[(size_t)cta * 32768 + m], s);
                __stcg(&g_psqs[(size_t)cta * 32768 + m], qq);
            }
        }

        if (t < 511) {
            PF_XG(t + 1);                  // independent of h; hides under barrier
            __syncthreads();               // h stores + hgS reads complete
            if (tid == 0)
                asm volatile("st.release.gpu.u32 [%0], %1;"
                             :: "l"(&g_arr[cta * 32]), "r"((unsigned)(t + 1)) : "memory");
            if (tid < NC) {
                unsigned v;
                do {
                    asm volatile("ld.acquire.gpu.u32 %0, [%1];"
                                 : "=r"(v) : "l"(&g_arr[tid * 32]) : "memory");
                } while (v < (unsigned)(t + 1));
            } else if (wid >= 4 && t >= 1) {
                // shadow: reduce LN partials of step t-1 while pollers spin
                int r = cta + (wid - 4) * NC;
                if (r < 64) {
                    int m = r * 512 + (t - 1);
                    float s = 0.f, qv = 0.f;
                    for (int c = lane; c < NC; c += 32) {
                        s  += __ldcg(&g_psum[(size_t)c * 32768 + m]);
                        qv += __ldcg(&g_psqs[(size_t)c * 32768 + m]);
                    }
#pragma unroll
                    for (int o = 16; o > 0; o >>= 1) {
                        s  += __shfl_xor_sync(0xffffffffu, s, o);
                        qv += __shfl_xor_sync(0xffffffffu, qv, o);
                    }
                    if (lane == 0) { __stcg(&g_sum[m], s); __stcg(&g_sqs[m], qv); }
                }
            }
            __syncthreads();
        }
    }
#undef PF_XG
}

// ---------------- final LayerNorm (H=128, eps=0) ----------------
template<int H>
__global__ void __launch_bounds__(128) ln_k(const float* __restrict__ gw,
                                            const float* __restrict__ bw,
                                            float* __restrict__ outp) {
    constexpr int PER = H / 128;
    __shared__ float red[8];
    const int row = blockIdx.x, tid = threadIdx.x;
    const float* p = g_actB + (size_t)row * H;
    float v[PER];
    float s = 0.f;
#pragma unroll
    for (int i = 0; i < PER; i++) { v[i] = p[tid + i * 128]; s += v[i]; }
#pragma unroll
    for (int o = 16; o > 0; o >>= 1) s += __shfl_xor_sync(0xffffffffu, s, o);
    if ((tid & 31) == 0) red[tid >> 5] = s;
    __syncthreads();
    float mean = (red[0] + red[1] + red[2] + red[3]) * (1.f / H);
    float s2 = 0.f;
#pragma unroll
    for (int i = 0; i < PER; i++) { float d = v[i] - mean; s2 += d * d; }
#pragma unroll
    for (int o = 16; o > 0; o >>= 1) s2 += __shfl_xor_sync(0xffffffffu, s2, o);
    if ((tid & 31) == 0) red[4 + (tid >> 5)] = s2;
    __syncthreads();
    float var = (red[4] + red[5] + red[6] + red[7]) * (1.f / H);
    float inv = rsqrtf(var);
#pragma unroll
    for (int i = 0; i < PER; i++) {
        int c = tid + i * 128;
        outp[(size_t)row * H + c] = (v[i] - mean) * inv * gw[c] + bw[c];
    }
}

// ---------------- driver ----------------
template<int H>
static void launch_rec(const float* Whh) {
    constexpr int SM = sizeof(unsigned) * ((H / 8) * 192 + 2 * 64 * 132)
                     + sizeof(float) * (3 * 64 * 40);
    cudaFuncSetAttribute(gru_rec<H>, cudaFuncAttributeMaxDynamicSharedMemorySize, SM);
    gru_rec<H><<<H / 8, 256, SM>>>(Whh);
}

extern "C" void kernel_launch(void* const* d_in, const int* in_sizes, int n_in,
                              void* d_out, int out_size) {
    (void)in_sizes; (void)n_in; (void)out_size;
    const float* x = (const float*)d_in[0];
    const float* Wih[6]; const float* Whh[6]; const float* gw[6]; const float* bw[6];
    for (int l = 0; l < 6; l++) {
        Wih[l] = (const float*)d_in[1 + 4 * l];
        Whh[l] = (const float*)d_in[2 + 4 * l];
        gw[l]  = (const float*)d_in[3 + 4 * l];
        bw[l]  = (const float*)d_in[4 + 4 * l];
    }
    float* actB;
    cudaGetSymbolAddress((void**)&actB, g_actB);

    static const int DIN[6] = {128, 256, 512, 1024, 512, 256};
    static const int HH[6]  = {256, 512, 1024, 512, 256, 128};

    for (int l = 0; l < 6; l++) {
        const int K = DIN[l], H = HH[l], N = 3 * H;
        const float* A = (l == 0) ? x : (const float*)actB;
        const float* gma = (l == 0) ? nullptr : gw[l - 1];
        const float* bta = (l == 0) ? nullptr : bw[l - 1];
        const int nprev = (l == 0) ? 0 : HH[l - 1] / 8;
        dim3 grid(N / 64, 256);
        if (l == 0) {
            gemm_xg<128, false><<<grid, 256>>>(A, Wih[l], N, gma, bta, nprev);
        } else {
            switch (K) {
                case 256:  gemm_xg<256, true><<<grid, 256>>>(A, Wih[l], N, gma, bta, nprev); break;
                case 512:  gemm_xg<512, true><<<grid, 256>>>(A, Wih[l], N, gma, bta, nprev); break;
                case 1024: gemm_xg<1024, true><<<grid, 256>>>(A, Wih[l], N, gma, bta, nprev); break;
            }
        }
        switch (H) {
            case 128:  launch_rec<128>(Whh[l]); break;
            case 256:  launch_rec<256>(Whh[l]); break;
            case 512:  launch_rec<512>(Whh[l]); break;
            case 1024: launch_rec<1024>(Whh[l]); break;
        }
    }
    ln_k<128><<<32768, 128>>>(gw[5], bw[5], (float*)d_out);
}

// round 10
// speedup vs baseline: 2.1258x; 1.0479x over previous
#include <cuda_runtime.h>
#include <cstdint>

// ---------------- static scratch (no allocs allowed) ----------------
__device__ float g_xg[32768 * 3072];        // input-projection buffer (max 3H=3072)
__device__ float g_actB[32768 * 1024];      // raw GRU outputs (pre-LN)
__device__ unsigned g_h[2][64 * 1024];      // double-buffered hidden state (tf32 bits)
__device__ float g_psum[128 * 32768];       // per-CTA partial row sums
__device__ float g_psqs[128 * 32768];       // per-CTA partial row sumsq
__device__ float g_sum[32768];              // reduced row sums
__device__ float g_sqs[32768];              // reduced row sumsq
__device__ unsigned g_arr[128 * 32];        // decentralized barrier slots (128B stride)

// ---------------- helpers ----------------
__device__ __forceinline__ unsigned f2tf(float x) {
    unsigned r; asm("cvt.rna.tf32.f32 %0, %1;" : "=r"(r) : "f"(x)); return r;
}
__device__ __forceinline__ void mma8(float* c, const unsigned* a, const unsigned* b) {
    asm volatile("mma.sync.aligned.m16n8k8.row.col.f32.tf32.tf32.f32 "
                 "{%0,%1,%2,%3}, {%4,%5,%6,%7}, {%8,%9}, {%0,%1,%2,%3};"
                 : "+f"(c[0]), "+f"(c[1]), "+f"(c[2]), "+f"(c[3])
                 : "r"(a[0]), "r"(a[1]), "r"(a[2]), "r"(a[3]),
                   "r"(b[0]), "r"(b[1]));
}

// ---------------- input-projection GEMM with optional fused LN ----------------
template<int K, bool LN>
__global__ void __launch_bounds__(256) gemm_xg(const float* __restrict__ A,
                                               const float* __restrict__ W,
                                               int N,
                                               const float* __restrict__ gma,
                                               const float* __restrict__ bta,
                                               int nprev) {
    __shared__ unsigned As[128 * 36];
    __shared__ unsigned Bs[64 * 36];
    __shared__ float gS[K], bS[K];
    __shared__ float rmS[128], rsS[128];

    const int m0 = blockIdx.y * 128;
    const int n0 = blockIdx.x * 64;
    const int tid = threadIdx.x;
    const int lane = tid & 31, wid = tid >> 5;
    const int wm = (wid & 3) * 32, wn = (wid >> 2) * 32;

    if (blockIdx.x == 0 && blockIdx.y == 0 && tid < 128)
        g_arr[tid * 32] = 0u;              // reset barrier slots for the next rec

    if (LN) {
        for (int i = tid; i < K; i += 256) { gS[i] = gma[i]; bS[i] = bta[i]; }
        if (tid < 128) {
            int m = m0 + tid;
            float s, q;
            if ((m & 511) >= 510) {
                s = 0.f; q = 0.f;
                for (int c = 0; c < nprev; c++) {
                    s += g_psum[(size_t)c * 32768 + m];
                    q += g_psqs[(size_t)c * 32768 + m];
                }
            } else {
                s = g_sum[m]; q = g_sqs[m];
            }
            float mean = s * (1.f / K);
            float var = q * (1.f / K) - mean * mean;
            rmS[tid] = mean;
            rsS[tid] = rsqrtf(var);
        }
        __syncthreads();
    }

    float acc[2][4][4];
#pragma unroll
    for (int i = 0; i < 2; i++)
#pragma unroll
        for (int j = 0; j < 4; j++)
#pragma unroll
            for (int k = 0; k < 4; k++) acc[i][j][k] = 0.f;

    const int lr = tid >> 3;
    const int lc = (tid & 7) * 4;

    for (int kc = 0; kc < K; kc += 32) {
#pragma unroll
        for (int i = 0; i < 4; i++) {
            int r = lr + i * 32;
            float4 v = *reinterpret_cast<const float4*>(&A[(size_t)(m0 + r) * K + kc + lc]);
            if (LN) {
                float mm = rmS[r], ss = rsS[r];
                int k = kc + lc;
                v.x = (v.x - mm) * ss * gS[k]     + bS[k];
                v.y = (v.y - mm) * ss * gS[k + 1] + bS[k + 1];
                v.z = (v.z - mm) * ss * gS[k + 2] + bS[k + 2];
                v.w = (v.w - mm) * ss * gS[k + 3] + bS[k + 3];
            }
            *reinterpret_cast<uint4*>(&As[r * 36 + lc]) =
                make_uint4(f2tf(v.x), f2tf(v.y), f2tf(v.z), f2tf(v.w));
        }
#pragma unroll
        for (int i = 0; i < 2; i++) {
            int r = lr + i * 32;
            float4 v = *reinterpret_cast<const float4*>(&W[(size_t)(n0 + r) * K + kc + lc]);
            *reinterpret_cast<uint4*>(&Bs[r * 36 + lc]) =
                make_uint4(f2tf(v.x), f2tf(v.y), f2tf(v.z), f2tf(v.w));
        }
        __syncthreads();
#pragma unroll
        for (int k8 = 0; k8 < 4; k8++) {
            const int kb = k8 * 8;
            unsigned a[2][4], b[4][2];
#pragma unroll
            for (int mf = 0; mf < 2; mf++) {
                int rb = wm + mf * 16 + (lane >> 2);
                a[mf][0] = As[rb * 36 + kb + (lane & 3)];
                a[mf][1] = As[(rb + 8) * 36 + kb + (lane & 3)];
                a[mf][2] = As[rb * 36 + kb + (lane & 3) + 4];
                a[mf][3] = As[(rb + 8) * 36 + kb + (lane & 3) + 4];
            }
#pragma unroll
            for (int nf = 0; nf < 4; nf++) {
                int cb = wn + nf * 8 + (lane >> 2);
                b[nf][0] = Bs[cb * 36 + kb + (lane & 3)];
                b[nf][1] = Bs[cb * 36 + kb + (lane & 3) + 4];
            }
#pragma unroll
            for (int mf = 0; mf < 2; mf++)
#pragma unroll
                for (int nf = 0; nf < 4; nf++)
                    mma8(acc[mf][nf], a[mf], b[nf]);
        }
        __syncthreads();
    }
#pragma unroll
    for (int mf = 0; mf < 2; mf++)
#pragma unroll
        for (int nf = 0; nf < 4; nf++) {
            int row = m0 + wm + mf * 16 + (lane >> 2);
            int col = n0 + wn + nf * 8 + 2 * (lane & 3);
            g_xg[(size_t)row * N + col]     = acc[mf][nf][0];
            g_xg[(size_t)row * N + col + 1] = acc[mf][nf][1];
            g_xg[(size_t)(row + 8) * N + col]     = acc[mf][nf][2];
            g_xg[(size_t)(row + 8) * N + col + 1] = acc[mf][nf][3];
        }
}

// ---------------- persistent GRU recurrence (sync-free mainloop) ----------------
// grid = H/8 CTAs, 256 threads, 8 warps: warp (mi = wid&1, kq = wid>>1).
// Warp (mi,kq) reads ONLY A rows [mi*32, mi*32+32) x k-quarter kq -> A is staged
// into WARP-PRIVATE double-buffered SMEM; no block syncs in the mainloop, only
// __syncwarp. Partials go to 4 per-kq hgS buffers; ONE block sync; epilogue sums
// them in kq order (bitwise-identical to the round-9 fold).
template<int H>
__global__ void __launch_bounds__(256, 1) gru_rec(const float* __restrict__ Whh) {
    constexpr int NCH = H / 128;         // 128-wide global chunks (kq covers 32 each)
    constexpr int NC  = H / 8;           // == gridDim.x  (<= 128)
    extern __shared__ unsigned char smem_raw[];
    unsigned* Wf = reinterpret_cast<unsigned*>(smem_raw);      // [H/8][3][64] packed B
    unsigned* Apriv = Wf + (H / 8) * 192;                      // 8 warps x 2 x [32][36]
    float* hgS = reinterpret_cast<float*>(Apriv + 8 * 2 * 1152); // 4 x [64][40]

    const float* xg = g_xg;
    float* y = g_actB;
    const int tid = threadIdx.x;
    const int lane = tid & 31, wid = tid >> 5;
    const int cta = blockIdx.x;
    const int c0 = cta * 8;
    const int q = lane >> 2, r4 = lane & 3;
    const int mi = wid & 1;              // m-half: rows mi*32..mi*32+31
    const int kq = wid >> 1;             // k-quarter within each 128-chunk

    // one-time: Whh slice -> SMEM in fragment-packed tf32 order (same as round 9)
    {
        constexpr int nf4 = H / 4;
        for (int idx = tid; idx < 24 * nf4; idx += 256) {
            int nn = idx / nf4;               // 0..23 : gate*8 + j
            int c4 = (idx % nf4) * 4;         // k, multiple of 4
            int gate = nn >> 3, j = nn & 7;
            float4 v = *reinterpret_cast<const float4*>(&Whh[(size_t)(gate * H + c0 + j) * H + c4]);
            int kb8 = c4 >> 3;
            int half = (c4 >> 2) & 1;
            unsigned* base = Wf + (kb8 * 3 + gate) * 64 + j * 8 + half;
            base[0] = f2tf(v.x); base[2] = f2tf(v.y);
            base[4] = f2tf(v.z); base[6] = f2tf(v.w);
        }
    }
    __syncthreads();

    const int col = tid & 7;             // epilogue: own column
    const int brow = tid >> 3;           // epilogue: batch rows brow, brow+32
    float hl[2] = {0.f, 0.f};
    float pxr[2], pxz[2], pxn[2];

#define PF_XG(TT) do { \
        _Pragma("unroll") \
        for (int it = 0; it < 2; it++) { \
            int b_ = brow + it * 32; \
            const float* xrow = xg + ((size_t)b_ * 512 + (TT)) * (size_t)(3 * H); \
            pxr[it] = __ldcs(xrow + c0 + col); \
            pxz[it] = __ldcs(xrow + H + c0 + col); \
            pxn[it] = __ldcs(xrow + 2 * H + c0 + col); \
        } } while (0)

    PF_XG(0);

    // warp-private staging map: lane covers rows (lane>>3)+i*4 (local), cols (lane&7)*4
    unsigned* Aw = Apriv + wid * 2 * 1152;
    const int plrow = lane >> 3;                  // local row base (adds i*4)
    const int pcol  = (lane & 7) * 4;             // word offset within 32-word band
    const int kb0   = kq * 32;                    // this warp's k-offset in each chunk

    for (int t = 0; t < 512; t++) {
        float acc[2][3][4];
#pragma unroll
        for (int mf = 0; mf < 2; mf++)
#pragma unroll
            for (int nf = 0; nf < 3; nf++)
#pragma unroll
                for (int k = 0; k < 4; k++) acc[mf][nf][k] = 0.f;

        if (t > 0) {
            const unsigned* hsrc = g_h[t & 1];
            uint4 pre[8];
#pragma unroll
            for (int i = 0; i < 8; i++)
                pre[i] = __ldcg(reinterpret_cast<const uint4*>(
                    &hsrc[(mi * 32 + plrow + i * 4) * H + kb0 + pcol]));
#pragma unroll
            for (int i = 0; i < 8; i++)
                *reinterpret_cast<uint4*>(&Aw[(plrow + i * 4) * 36 + pcol]) = pre[i];
            __syncwarp();

            for (int ch = 0; ch < NCH; ch++) {
                if (ch + 1 < NCH) {
                    const int k0 = (ch + 1) * 128 + kb0;
#pragma unroll
                    for (int i = 0; i < 8; i++)
                        pre[i] = __ldcg(reinterpret_cast<const uint4*>(
                            &hsrc[(mi * 32 + plrow + i * 4) * H + k0 + pcol]));
                }
                const unsigned* Ab = Aw + (ch & 1) * 1152;
#pragma unroll
                for (int k8 = 0; k8 < 4; k8++) {
                    const int kb = k8 * 8;
                    const int g8 = ch * 16 + kq * 4 + k8;     // global k8 index
                    unsigned a0[4], a1[4];
                    a0[0] = Ab[q * 36 + kb + r4];
                    a0[1] = Ab[(q + 8) * 36 + kb + r4];
                    a0[2] = Ab[q * 36 + kb + r4 + 4];
                    a0[3] = Ab[(q + 8) * 36 + kb + r4 + 4];
                    a1[0] = Ab[(q + 16) * 36 + kb + r4];
                    a1[1] = Ab[(q + 24) * 36 + kb + r4];
                    a1[2] = Ab[(q + 16) * 36 + kb + r4 + 4];
                    a1[3] = Ab[(q + 24) * 36 + kb + r4 + 4];
#pragma unroll
                    for (int nf = 0; nf < 3; nf++) {
                        uint2 bb = *reinterpret_cast<const uint2*>(&Wf[(g8 * 3 + nf) * 64 + lane * 2]);
                        unsigned bfr[2] = {bb.x, bb.y};
                        mma8(acc[0][nf], a0, bfr);
                        mma8(acc[1][nf], a1, bfr);
                    }
                }
                if (ch + 1 < NCH) {
                    unsigned* Bb = Aw + ((ch + 1) & 1) * 1152;
#pragma unroll
                    for (int i = 0; i < 8; i++)
                        *reinterpret_cast<uint4*>(&Bb[(plrow + i * 4) * 36 + pcol]) = pre[i];
                    __syncwarp();
                }
            }
        }
        // ---- all warps store their K-partials into their kq buffer ----
        {
            float* dst = hgS + kq * 2560;
#pragma unroll
            for (int mf = 0; mf < 2; mf++)
#pragma unroll
                for (int nf = 0; nf < 3; nf++) {
                    int row = mi * 32 + mf * 16 + q;
                    int cc = nf * 8 + 2 * r4;
                    dst[row * 40 + cc]           = acc[mf][nf][0];
                    dst[row * 40 + cc + 1]       = acc[mf][nf][1];
                    dst[(row + 8) * 40 + cc]     = acc[mf][nf][2];
                    dst[(row + 8) * 40 + cc + 1] = acc[mf][nf][3];
                }
        }
        __syncthreads();

        // ---- gate epilogue: sums 4 kq buffers in kq order (== round-9 fold order) ----
        unsigned* hdst = g_h[(t + 1) & 1];
#pragma unroll
        for (int it = 0; it < 2; it++) {
            int b = brow + it * 32;
            float hr = hgS[b * 40 + col]      + hgS[2560 + b * 40 + col]
                     + hgS[5120 + b * 40 + col]      + hgS[7680 + b * 40 + col];
            float hz = hgS[b * 40 + 8 + col]  + hgS[2560 + b * 40 + 8 + col]
                     + hgS[5120 + b * 40 + 8 + col]  + hgS[7680 + b * 40 + 8 + col];
            float hn = hgS[b * 40 + 16 + col] + hgS[2560 + b * 40 + 16 + col]
                     + hgS[5120 + b * 40 + 16 + col] + hgS[7680 + b * 40 + 16 + col];
            float r = 1.f / (1.f + __expf(-(pxr[it] + hr)));
            float z = 1.f / (1.f + __expf(-(pxz[it] + hz)));
            float n = tanhf(pxn[it] + r * hn);
            float h2 = (1.f - z) * n + z * hl[it];
            hl[it] = h2;
            size_t m = (size_t)b * 512 + t;
            y[m * (size_t)H + c0 + col] = h2;
            __stcg(&hdst[b * H + c0 + col], f2tf(h2));
            float s = h2, qq = h2 * h2;
#pragma unroll
            for (int o = 4; o > 0; o >>= 1) {
                s  += __shfl_down_sync(0xffffffffu, s, o, 8);
                qq += __shfl_down_sync(0xffffffffu, qq, o, 8);
            }
            if (col == 0) {
                __stcg(&g_psum[(size_t)cta * 32768 + m], s);
                __stcg(&g_psqs[(size_t)cta * 32768 + m], qq);
            }
        }

        if (t < 511) {
            PF_XG(t + 1);                  // independent of h; hides under barrier
            __syncthreads();               // h stores + hgS reads complete
            if (tid == 0)
                asm volatile("st.release.gpu.u32 [%0], %1;"
                             :: "l"(&g_arr[cta * 32]), "r"((unsigned)(t + 1)) : "memory");
            if (tid < NC) {
                unsigned v;
                do {
                    asm volatile("ld.acquire.gpu.u32 %0, [%1];"
                                 : "=r"(v) : "l"(&g_arr[tid * 32]) : "memory");
                } while (v < (unsigned)(t + 1));
            } else if (wid >= 4 && t >= 1) {
                // shadow: reduce LN partials of step t-1 while pollers spin
                int r = cta + (wid - 4) * NC;
                if (r < 64) {
                    int m = r * 512 + (t - 1);
                    float s = 0.f, qv = 0.f;
                    for (int c = lane; c < NC; c += 32) {
                        s  += __ldcg(&g_psum[(size_t)c * 32768 + m]);
                        qv += __ldcg(&g_psqs[(size_t)c * 32768 + m]);
                    }
#pragma unroll
                    for (int o = 16; o > 0; o >>= 1) {
                        s  += __shfl_xor_sync(0xffffffffu, s, o);
                        qv += __shfl_xor_sync(0xffffffffu, qv, o);
                    }
                    if (lane == 0) { __stcg(&g_sum[m], s); __stcg(&g_sqs[m], qv); }
                }
            }
            __syncthreads();
        }
    }
#undef PF_XG
}

// ---------------- final LayerNorm (H=128, eps=0) ----------------
template<int H>
__global__ void __launch_bounds__(128) ln_k(const float* __restrict__ gw,
                                            const float* __restrict__ bw,
                                            float* __restrict__ outp) {
    constexpr int PER = H / 128;
    __shared__ float red[8];
    const int row = blockIdx.x, tid = threadIdx.x;
    const float* p = g_actB + (size_t)row * H;
    float v[PER];
    float s = 0.f;
#pragma unroll
    for (int i = 0; i < PER; i++) { v[i] = p[tid + i * 128]; s += v[i]; }
#pragma unroll
    for (int o = 16; o > 0; o >>= 1) s += __shfl_xor_sync(0xffffffffu, s, o);
    if ((tid & 31) == 0) red[tid >> 5] = s;
    __syncthreads();
    float mean = (red[0] + red[1] + red[2] + red[3]) * (1.f / H);
    float s2 = 0.f;
#pragma unroll
    for (int i = 0; i < PER; i++) { float d = v[i] - mean; s2 += d * d; }
#pragma unroll
    for (int o = 16; o > 0; o >>= 1) s2 += __shfl_xor_sync(0xffffffffu, s2, o);
    if ((tid & 31) == 0) red[4 + (tid >> 5)] = s2;
    __syncthreads();
    float var = (red[4] + red[5] + red[6] + red[7]) * (1.f / H);
    float inv = rsqrtf(var);
#pragma unroll
    for (int i = 0; i < PER; i++) {
        int c = tid + i * 128;
        outp[(size_t)row * H + c] = (v[i] - mean) * inv * gw[c] + bw[c];
    }
}

// ---------------- driver ----------------
template<int H>
static void launch_rec(const float* Whh) {
    constexpr int SM = sizeof(unsigned) * ((H / 8) * 192 + 8 * 2 * 1152)
                     + sizeof(float) * (4 * 64 * 40);
    cudaFuncSetAttribute(gru_rec<H>, cudaFuncAttributeMaxDynamicSharedMemorySize, SM);
    gru_rec<H><<<H / 8, 256, SM>>>(Whh);
}

extern "C" void kernel_launch(void* const* d_in, const int* in_sizes, int n_in,
                              void* d_out, int out_size) {
    (void)in_sizes; (void)n_in; (void)out_size;
    const float* x = (const float*)d_in[0];
    const float* Wih[6]; const float* Whh[6]; const float* gw[6]; const float* bw[6];
    for (int l = 0; l < 6; l++) {
        Wih[l] = (const float*)d_in[1 + 4 * l];
        Whh[l] = (const float*)d_in[2 + 4 * l];
        gw[l]  = (const float*)d_in[3 + 4 * l];
        bw[l]  = (const float*)d_in[4 + 4 * l];
    }
    float* actB;
    cudaGetSymbolAddress((void**)&actB, g_actB);

    static const int DIN[6] = {128, 256, 512, 1024, 512, 256};
    static const int HH[6]  = {256, 512, 1024, 512, 256, 128};

    for (int l = 0; l < 6; l++) {
        const int K = DIN[l], H = HH[l], N = 3 * H;
        const float* A = (l == 0) ? x : (const float*)actB;
        const float* gma = (l == 0) ? nullptr : gw[l - 1];
        const float* bta = (l == 0) ? nullptr : bw[l - 1];
        const int nprev = (l == 0) ? 0 : HH[l - 1] / 8;
        dim3 grid(N / 64, 256);
        if (l == 0) {
            gemm_xg<128, false><<<grid, 256>>>(A, Wih[l], N, gma, bta, nprev);
        } else {
            switch (K) {
                case 256:  gemm_xg<256, true><<<grid, 256>>>(A, Wih[l], N, gma, bta, nprev); break;
                case 512:  gemm_xg<512, true><<<grid, 256>>>(A, Wih[l], N, gma, bta, nprev); break;
                case 1024: gemm_xg<1024, true><<<grid, 256>>>(A, Wih[l], N, gma, bta, nprev); break;
            }
        }
        switch (H) {
            case 128:  launch_rec<128>(Whh[l]); break;
            case 256:  launch_rec<256>(Whh[l]); break;
            case 512:  launch_rec<512>(Whh[l]); break;
            case 1024: launch_rec<1024>(Whh[l]); break;
        }
    }
    ln_k<128><<<32768, 128>>>(gw[5], bw[5], (float*)d_out);
}